// round 1
// baseline (speedup 1.0000x reference)
#include <cuda_runtime.h>
#include <math.h>

#define B_ 2
#define S_ 4096
#define E_ 768
#define H_ 12
#define D_ 64
#define C_ 64
#define R_ 256
#define MTOT (B_*S_)

// Scratch (device globals: no runtime allocation allowed)
__device__ float g_q[B_*H_*S_*D_];
__device__ float g_k[B_*H_*S_*D_];
__device__ float g_v[B_*H_*S_*D_];
__device__ float g_ctx[MTOT*E_];

// ---------------------------------------------------------------------------
// QKV projection GEMM: out[m,n] = X[m,:] @ W[:,n] + bias[n]
// 64x64 tile, BK=16, 256 threads, 4x4 register tile per thread.
// blockIdx.z selects q/k/v; epilogue remaps to (b,h,s,d) layout, scales q.
// ---------------------------------------------------------------------------
__global__ __launch_bounds__(256)
void qkv_kernel(const float* __restrict__ X,
                const float* __restrict__ Wq, const float* __restrict__ bq,
                const float* __restrict__ Wk, const float* __restrict__ bk,
                const float* __restrict__ Wv, const float* __restrict__ bv)
{
    __shared__ float As[16][68];   // [k][m], padded stride 68
    __shared__ float Bs[16][64];   // [k][n]

    const int z = blockIdx.z;
    const float* __restrict__ W    = (z == 0) ? Wq : (z == 1) ? Wk : Wv;
    const float* __restrict__ bias = (z == 0) ? bq : (z == 1) ? bk : bv;
    float* out = (z == 0) ? g_q : (z == 1) ? g_k : g_v;
    const float scale = (z == 0) ? 0.125f : 1.0f;   // 1/sqrt(64) for q

    const int tid = threadIdx.x;
    const int tx = tid & 15, ty = tid >> 4;
    const int m0 = blockIdx.y * 64, n0 = blockIdx.x * 64;

    const int arow = tid >> 2, acol = (tid & 3) * 4;
    const int brow = tid >> 4, bcol = (tid & 15) * 4;

    float acc[4][4] = {};

    const float* aPtr = X + (m0 + arow) * E_ + acol;
    const float* bPtr = W + brow * E_ + n0 + bcol;
    float4 aReg = *(const float4*)aPtr;
    float4 bReg = *(const float4*)bPtr;

    for (int k0 = 0; k0 < E_; k0 += 16) {
        __syncthreads();
        As[acol + 0][arow] = aReg.x;
        As[acol + 1][arow] = aReg.y;
        As[acol + 2][arow] = aReg.z;
        As[acol + 3][arow] = aReg.w;
        *(float4*)&Bs[brow][bcol] = bReg;
        __syncthreads();
        if (k0 + 16 < E_) {
            aReg = *(const float4*)(aPtr + k0 + 16);
            bReg = *(const float4*)(bPtr + (size_t)(k0 + 16) * E_);
        }
        #pragma unroll
        for (int k = 0; k < 16; k++) {
            float4 a4 = *(float4*)&As[k][ty * 4];
            float4 b4 = *(float4*)&Bs[k][tx * 4];
            float av[4] = {a4.x, a4.y, a4.z, a4.w};
            float bw[4] = {b4.x, b4.y, b4.z, b4.w};
            #pragma unroll
            for (int i = 0; i < 4; i++)
                #pragma unroll
                for (int j = 0; j < 4; j++)
                    acc[i][j] += av[i] * bw[j];
        }
    }

    const int n  = n0 + tx * 4;
    const int hh = n >> 6, d = n & 63;
    const float4 bias4 = *(const float4*)&bias[n];
    #pragma unroll
    for (int i = 0; i < 4; i++) {
        int m    = m0 + ty * 4 + i;
        int bb   = m >> 12;          // m / S_
        int srow = m & (S_ - 1);
        float4 o;
        o.x = (acc[i][0] + bias4.x) * scale;
        o.y = (acc[i][1] + bias4.y) * scale;
        o.z = (acc[i][2] + bias4.z) * scale;
        o.w = (acc[i][3] + bias4.w) * scale;
        *(float4*)&out[((bb * H_ + hh) * S_ + srow) * D_ + d] = o;
    }
}

// ---------------------------------------------------------------------------
// Output projection GEMM: d_out[m,n] = g_ctx[m,:] @ Wo[:,n] + bo[n]
// ---------------------------------------------------------------------------
__global__ __launch_bounds__(256)
void proj_kernel(const float* __restrict__ Wo, const float* __restrict__ bo,
                 float* __restrict__ out)
{
    __shared__ float As[16][68];
    __shared__ float Bs[16][64];

    const float* __restrict__ X = g_ctx;

    const int tid = threadIdx.x;
    const int tx = tid & 15, ty = tid >> 4;
    const int m0 = blockIdx.y * 64, n0 = blockIdx.x * 64;

    const int arow = tid >> 2, acol = (tid & 3) * 4;
    const int brow = tid >> 4, bcol = (tid & 15) * 4;

    float acc[4][4] = {};

    const float* aPtr = X + (m0 + arow) * E_ + acol;
    const float* bPtr = Wo + brow * E_ + n0 + bcol;
    float4 aReg = *(const float4*)aPtr;
    float4 bReg = *(const float4*)bPtr;

    for (int k0 = 0; k0 < E_; k0 += 16) {
        __syncthreads();
        As[acol + 0][arow] = aReg.x;
        As[acol + 1][arow] = aReg.y;
        As[acol + 2][arow] = aReg.z;
        As[acol + 3][arow] = aReg.w;
        *(float4*)&Bs[brow][bcol] = bReg;
        __syncthreads();
        if (k0 + 16 < E_) {
            aReg = *(const float4*)(aPtr + k0 + 16);
            bReg = *(const float4*)(bPtr + (size_t)(k0 + 16) * E_);
        }
        #pragma unroll
        for (int k = 0; k < 16; k++) {
            float4 a4 = *(float4*)&As[k][ty * 4];
            float4 b4 = *(float4*)&Bs[k][tx * 4];
            float av[4] = {a4.x, a4.y, a4.z, a4.w};
            float bw[4] = {b4.x, b4.y, b4.z, b4.w};
            #pragma unroll
            for (int i = 0; i < 4; i++)
                #pragma unroll
                for (int j = 0; j < 4; j++)
                    acc[i][j] += av[i] * bw[j];
        }
    }

    const int n = n0 + tx * 4;
    const float4 bias4 = *(const float4*)&bo[n];
    #pragma unroll
    for (int i = 0; i < 4; i++) {
        int m = m0 + ty * 4 + i;
        float4 o;
        o.x = acc[i][0] + bias4.x;
        o.y = acc[i][1] + bias4.y;
        o.z = acc[i][2] + bias4.z;
        o.w = acc[i][3] + bias4.w;
        *(float4*)&out[(size_t)m * E_ + n] = o;
    }
}

// ---------------------------------------------------------------------------
// Local attention, streaming softmax over 9 key-tiles of 64.
// One CTA per (chunk, h, b). 256 threads:
//   thread -> a = tid>>3 (query rows 2a, 2a+1), kg = tid&7
//   QK: keys kg + 8*j (j=0..7)   PV: d columns kg*8 .. kg*8+7
// All key tiles are 64-aligned -> fully valid or fully invalid (skip).
// ---------------------------------------------------------------------------
#define ATTN_SMEM_BYTES (4 * 64 * 68 * 4)

__global__ __launch_bounds__(256)
void attn_kernel()
{
    extern __shared__ float sm[];
    float* Qs = sm;                 // [64][68]
    float* Ks = sm + 64 * 68;
    float* Vs = sm + 2 * 64 * 68;
    float* Ps = sm + 3 * 64 * 68;

    const int tid = threadIdx.x;
    const int nchunk = blockIdx.x, h = blockIdx.y, b = blockIdx.z;
    const int a  = tid >> 3;
    const int kg = tid & 7;
    const int r0 = 2 * a, r1 = 2 * a + 1;
    const int chunkStart = nchunk * C_;
    const int base = (b * H_ + h) * S_ * D_;

    // cooperative load map: 64 rows x 64 cols, 16 floats/thread
    const int lrow = tid >> 2;
    const int lcol = (tid & 3) * 16;

    {   // load Q chunk
        const float* src = g_q + base + (chunkStart + lrow) * D_ + lcol;
        float* dst = Qs + lrow * 68 + lcol;
        *(float4*)(dst + 0)  = *(const float4*)(src + 0);
        *(float4*)(dst + 4)  = *(const float4*)(src + 4);
        *(float4*)(dst + 8)  = *(const float4*)(src + 8);
        *(float4*)(dst + 12) = *(const float4*)(src + 12);
    }

    float m0v = -INFINITY, m1v = -INFINITY;
    float l0 = 0.f, l1 = 0.f;
    float acc0[8], acc1[8];
    #pragma unroll
    for (int i = 0; i < 8; i++) { acc0[i] = 0.f; acc1[i] = 0.f; }

    for (int t = 0; t < 9; t++) {
        const int tileStart = chunkStart - R_ + t * C_;
        if (tileStart < 0 || tileStart >= S_) continue;   // uniform per block

        __syncthreads();   // previous tile fully consumed
        {
            const int pos = tileStart + lrow;
            const float* ksrc = g_k + base + pos * D_ + lcol;
            const float* vsrc = g_v + base + pos * D_ + lcol;
            float* kdst = Ks + lrow * 68 + lcol;
            float* vdst = Vs + lrow * 68 + lcol;
            *(float4*)(kdst + 0)  = *(const float4*)(ksrc + 0);
            *(float4*)(kdst + 4)  = *(const float4*)(ksrc + 4);
            *(float4*)(kdst + 8)  = *(const float4*)(ksrc + 8);
            *(float4*)(kdst + 12) = *(const float4*)(ksrc + 12);
            *(float4*)(vdst + 0)  = *(const float4*)(vsrc + 0);
            *(float4*)(vdst + 4)  = *(const float4*)(vsrc + 4);
            *(float4*)(vdst + 8)  = *(const float4*)(vsrc + 8);
            *(float4*)(vdst + 12) = *(const float4*)(vsrc + 12);
        }
        __syncthreads();

        // ---- scores: s[r][j] for keys kg + 8j ----
        float s0[8], s1[8];
        #pragma unroll
        for (int j = 0; j < 8; j++) { s0[j] = 0.f; s1[j] = 0.f; }

        #pragma unroll
        for (int kk = 0; kk < 64; kk += 4) {
            float4 q0 = *(float4*)&Qs[r0 * 68 + kk];
            float4 q1 = *(float4*)&Qs[r1 * 68 + kk];
            #pragma unroll
            for (int j = 0; j < 8; j++) {
                float4 k4 = *(float4*)&Ks[(kg + 8 * j) * 68 + kk];
                s0[j] += q0.x * k4.x + q0.y * k4.y + q0.z * k4.z + q0.w * k4.w;
                s1[j] += q1.x * k4.x + q1.y * k4.y + q1.z * k4.z + q1.w * k4.w;
            }
        }

        // ---- online softmax (reduce across 8 kg lanes) ----
        float t0 = -INFINITY, t1 = -INFINITY;
        #pragma unroll
        for (int j = 0; j < 8; j++) { t0 = fmaxf(t0, s0[j]); t1 = fmaxf(t1, s1[j]); }
        #pragma unroll
        for (int off = 1; off < 8; off <<= 1) {
            t0 = fmaxf(t0, __shfl_xor_sync(0xffffffffu, t0, off));
            t1 = fmaxf(t1, __shfl_xor_sync(0xffffffffu, t1, off));
        }
        const float mn0 = fmaxf(m0v, t0);
        const float mn1 = fmaxf(m1v, t1);
        const float rs0 = __expf(m0v - mn0);
        const float rs1 = __expf(m1v - mn1);

        float ls0 = 0.f, ls1 = 0.f;
        #pragma unroll
        for (int j = 0; j < 8; j++) {
            float p0 = __expf(s0[j] - mn0);
            float p1 = __expf(s1[j] - mn1);
            Ps[r0 * 68 + kg + 8 * j] = p0;
            Ps[r1 * 68 + kg + 8 * j] = p1;
            ls0 += p0; ls1 += p1;
        }
        #pragma unroll
        for (int off = 1; off < 8; off <<= 1) {
            ls0 += __shfl_xor_sync(0xffffffffu, ls0, off);
            ls1 += __shfl_xor_sync(0xffffffffu, ls1, off);
        }
        l0 = l0 * rs0 + ls0;  m0v = mn0;
        l1 = l1 * rs1 + ls1;  m1v = mn1;
        #pragma unroll
        for (int i = 0; i < 8; i++) { acc0[i] *= rs0; acc1[i] *= rs1; }

        __syncwarp();   // P row written only by own-warp lanes

        // ---- PV accumulate ----
        #pragma unroll 4
        for (int k = 0; k < 64; k++) {
            float p0 = Ps[r0 * 68 + k];
            float p1 = Ps[r1 * 68 + k];
            float4 va = *(float4*)&Vs[k * 68 + kg * 8];
            float4 vb = *(float4*)&Vs[k * 68 + kg * 8 + 4];
            acc0[0] += p0 * va.x; acc0[1] += p0 * va.y; acc0[2] += p0 * va.z; acc0[3] += p0 * va.w;
            acc0[4] += p0 * vb.x; acc0[5] += p0 * vb.y; acc0[6] += p0 * vb.z; acc0[7] += p0 * vb.w;
            acc1[0] += p1 * va.x; acc1[1] += p1 * va.y; acc1[2] += p1 * va.z; acc1[3] += p1 * va.w;
            acc1[4] += p1 * vb.x; acc1[5] += p1 * vb.y; acc1[6] += p1 * vb.z; acc1[7] += p1 * vb.w;
        }
    }

    // ---- write ctx: (b, s, h*64+d) ----
    const float inv0 = 1.f / l0;
    const float inv1 = 1.f / l1;
    const int e0 = h * 64 + kg * 8;
    float* dst0 = g_ctx + (b * S_ + chunkStart + r0) * E_ + e0;
    float* dst1 = g_ctx + (b * S_ + chunkStart + r1) * E_ + e0;
    float4 o;
    o.x = acc0[0] * inv0; o.y = acc0[1] * inv0; o.z = acc0[2] * inv0; o.w = acc0[3] * inv0;
    *(float4*)(dst0 + 0) = o;
    o.x = acc0[4] * inv0; o.y = acc0[5] * inv0; o.z = acc0[6] * inv0; o.w = acc0[7] * inv0;
    *(float4*)(dst0 + 4) = o;
    o.x = acc1[0] * inv1; o.y = acc1[1] * inv1; o.z = acc1[2] * inv1; o.w = acc1[3] * inv1;
    *(float4*)(dst1 + 0) = o;
    o.x = acc1[4] * inv1; o.y = acc1[5] * inv1; o.z = acc1[6] * inv1; o.w = acc1[7] * inv1;
    *(float4*)(dst1 + 4) = o;
}

// ---------------------------------------------------------------------------
extern "C" void kernel_launch(void* const* d_in, const int* in_sizes, int n_in,
                              void* d_out, int out_size)
{
    const float* X  = (const float*)d_in[0];
    const float* Wq = (const float*)d_in[1];
    const float* bq = (const float*)d_in[2];
    const float* Wk = (const float*)d_in[3];
    const float* bk = (const float*)d_in[4];
    const float* Wv = (const float*)d_in[5];
    const float* bv = (const float*)d_in[6];
    const float* Wo = (const float*)d_in[7];
    const float* bo = (const float*)d_in[8];
    float* out = (float*)d_out;

    cudaFuncSetAttribute(attn_kernel,
                         cudaFuncAttributeMaxDynamicSharedMemorySize,
                         ATTN_SMEM_BYTES);

    dim3 gq(E_ / 64, MTOT / 64, 3);
    qkv_kernel<<<gq, 256>>>(X, Wq, bq, Wk, bk, Wv, bv);

    attn_kernel<<<dim3(S_ / C_, H_, B_), 256, ATTN_SMEM_BYTES>>>();

    proj_kernel<<<dim3(E_ / 64, MTOT / 64), 256>>>(Wo, bo, out);
}

// round 2
// speedup vs baseline: 1.2454x; 1.2454x over previous
#include <cuda_runtime.h>
#include <math.h>

#define B_ 2
#define S_ 4096
#define E_ 768
#define H_ 12
#define D_ 64
#define C_ 64
#define R_ 256
#define MTOT (B_*S_)

// Scratch (device globals: no runtime allocation allowed)
__device__ float g_q[B_*H_*S_*D_];
__device__ float g_k[B_*H_*S_*D_];
__device__ float g_v[B_*H_*S_*D_];
__device__ float g_ctx[MTOT*E_];

// ---------------------------------------------------------------------------
// SGEMM core: 128x128 tile, BK=16, 256 threads, 8x8 register micro-tile.
// Per k-step: 16 smem floats -> 64 FMAs (8 FLOP/float).
// ---------------------------------------------------------------------------
#define BM 128
#define BN 128
#define BKK 16

// qkv: fused over N=2304 (q|k|v). grid.x = 18 (6 n-tiles per matrix), grid.y = 64.
__global__ __launch_bounds__(256)
void qkv_kernel(const float* __restrict__ X,
                const float* __restrict__ Wq, const float* __restrict__ bq,
                const float* __restrict__ Wk, const float* __restrict__ bk,
                const float* __restrict__ Wv, const float* __restrict__ bv)
{
    __shared__ float As[BKK][BM + 4];   // transposed: As[k][m]
    __shared__ float Bs[BKK][BN];       // Bs[k][n]

    const int z    = blockIdx.x / 6;
    const int nblk = blockIdx.x % 6;
    const float* __restrict__ W    = (z == 0) ? Wq : (z == 1) ? Wk : Wv;
    const float* __restrict__ bias = (z == 0) ? bq : (z == 1) ? bk : bv;
    float* out = (z == 0) ? g_q : (z == 1) ? g_k : g_v;
    const float scale = (z == 0) ? 0.125f : 1.0f;

    const int tid = threadIdx.x;
    const int tx = tid & 15, ty = tid >> 4;
    const int m0 = blockIdx.y * BM, n0 = nblk * BN;

    // A load map: 128 rows x 16 cols, 2 float4 per thread
    const int ar = tid >> 1, ac = (tid & 1) * 8;
    // B load map: 16 rows x 128 cols, 2 float4 per thread
    const int br = tid >> 4, bc = (tid & 15) * 8;

    const float* aPtr = X + (size_t)(m0 + ar) * E_ + ac;
    const float* bPtr = W + (size_t)br * E_ + n0 + bc;

    float4 a0 = *(const float4*)(aPtr + 0);
    float4 a1 = *(const float4*)(aPtr + 4);
    float4 b0 = *(const float4*)(bPtr + 0);
    float4 b1 = *(const float4*)(bPtr + 4);

    float acc[8][8] = {};

    for (int k0 = 0; k0 < E_; k0 += BKK) {
        __syncthreads();
        As[ac + 0][ar] = a0.x; As[ac + 1][ar] = a0.y;
        As[ac + 2][ar] = a0.z; As[ac + 3][ar] = a0.w;
        As[ac + 4][ar] = a1.x; As[ac + 5][ar] = a1.y;
        As[ac + 6][ar] = a1.z; As[ac + 7][ar] = a1.w;
        *(float4*)&Bs[br][bc + 0] = b0;
        *(float4*)&Bs[br][bc + 4] = b1;
        __syncthreads();
        if (k0 + BKK < E_) {
            a0 = *(const float4*)(aPtr + k0 + BKK + 0);
            a1 = *(const float4*)(aPtr + k0 + BKK + 4);
            b0 = *(const float4*)(bPtr + (size_t)(k0 + BKK) * E_ + 0);
            b1 = *(const float4*)(bPtr + (size_t)(k0 + BKK) * E_ + 4);
        }
        #pragma unroll
        for (int kk = 0; kk < BKK; kk++) {
            float4 alo = *(float4*)&As[kk][ty * 8];
            float4 ahi = *(float4*)&As[kk][ty * 8 + 4];
            float4 blo = *(float4*)&Bs[kk][tx * 8];
            float4 bhi = *(float4*)&Bs[kk][tx * 8 + 4];
            float av[8] = {alo.x, alo.y, alo.z, alo.w, ahi.x, ahi.y, ahi.z, ahi.w};
            float bv_[8] = {blo.x, blo.y, blo.z, blo.w, bhi.x, bhi.y, bhi.z, bhi.w};
            #pragma unroll
            for (int i = 0; i < 8; i++)
                #pragma unroll
                for (int j = 0; j < 8; j++)
                    acc[i][j] += av[i] * bv_[j];
        }
    }

    // epilogue: remap to (b,h,s,d), add bias, scale q
    const int ncol = n0 + tx * 8;       // 0..767 within this matrix
    const int hh = ncol >> 6, d0 = ncol & 63;
    const float4 bi0 = *(const float4*)&bias[ncol];
    const float4 bi1 = *(const float4*)&bias[ncol + 4];
    #pragma unroll
    for (int i = 0; i < 8; i++) {
        const int m  = m0 + ty * 8 + i;
        const int bb = m >> 12;
        const int s  = m & (S_ - 1);
        float* dst = out + ((size_t)(bb * H_ + hh) * S_ + s) * D_ + d0;
        float4 o;
        o.x = (acc[i][0] + bi0.x) * scale; o.y = (acc[i][1] + bi0.y) * scale;
        o.z = (acc[i][2] + bi0.z) * scale; o.w = (acc[i][3] + bi0.w) * scale;
        *(float4*)(dst + 0) = o;
        o.x = (acc[i][4] + bi1.x) * scale; o.y = (acc[i][5] + bi1.y) * scale;
        o.z = (acc[i][6] + bi1.z) * scale; o.w = (acc[i][7] + bi1.w) * scale;
        *(float4*)(dst + 4) = o;
    }
}

// out-projection: same core, plain epilogue
__global__ __launch_bounds__(256)
void proj_kernel(const float* __restrict__ Wo, const float* __restrict__ bo,
                 float* __restrict__ out)
{
    __shared__ float As[BKK][BM + 4];
    __shared__ float Bs[BKK][BN];

    const float* __restrict__ X = g_ctx;

    const int tid = threadIdx.x;
    const int tx = tid & 15, ty = tid >> 4;
    const int m0 = blockIdx.y * BM, n0 = blockIdx.x * BN;

    const int ar = tid >> 1, ac = (tid & 1) * 8;
    const int br = tid >> 4, bc = (tid & 15) * 8;

    const float* aPtr = X + (size_t)(m0 + ar) * E_ + ac;
    const float* bPtr = Wo + (size_t)br * E_ + n0 + bc;

    float4 a0 = *(const float4*)(aPtr + 0);
    float4 a1 = *(const float4*)(aPtr + 4);
    float4 b0 = *(const float4*)(bPtr + 0);
    float4 b1 = *(const float4*)(bPtr + 4);

    float acc[8][8] = {};

    for (int k0 = 0; k0 < E_; k0 += BKK) {
        __syncthreads();
        As[ac + 0][ar] = a0.x; As[ac + 1][ar] = a0.y;
        As[ac + 2][ar] = a0.z; As[ac + 3][ar] = a0.w;
        As[ac + 4][ar] = a1.x; As[ac + 5][ar] = a1.y;
        As[ac + 6][ar] = a1.z; As[ac + 7][ar] = a1.w;
        *(float4*)&Bs[br][bc + 0] = b0;
        *(float4*)&Bs[br][bc + 4] = b1;
        __syncthreads();
        if (k0 + BKK < E_) {
            a0 = *(const float4*)(aPtr + k0 + BKK + 0);
            a1 = *(const float4*)(aPtr + k0 + BKK + 4);
            b0 = *(const float4*)(bPtr + (size_t)(k0 + BKK) * E_ + 0);
            b1 = *(const float4*)(bPtr + (size_t)(k0 + BKK) * E_ + 4);
        }
        #pragma unroll
        for (int kk = 0; kk < BKK; kk++) {
            float4 alo = *(float4*)&As[kk][ty * 8];
            float4 ahi = *(float4*)&As[kk][ty * 8 + 4];
            float4 blo = *(float4*)&Bs[kk][tx * 8];
            float4 bhi = *(float4*)&Bs[kk][tx * 8 + 4];
            float av[8] = {alo.x, alo.y, alo.z, alo.w, ahi.x, ahi.y, ahi.z, ahi.w};
            float bv_[8] = {blo.x, blo.y, blo.z, blo.w, bhi.x, bhi.y, bhi.z, bhi.w};
            #pragma unroll
            for (int i = 0; i < 8; i++)
                #pragma unroll
                for (int j = 0; j < 8; j++)
                    acc[i][j] += av[i] * bv_[j];
        }
    }

    const int n = n0 + tx * 8;
    const float4 bi0 = *(const float4*)&bo[n];
    const float4 bi1 = *(const float4*)&bo[n + 4];
    #pragma unroll
    for (int i = 0; i < 8; i++) {
        const int m = m0 + ty * 8 + i;
        float* dst = out + (size_t)m * E_ + n;
        float4 o;
        o.x = acc[i][0] + bi0.x; o.y = acc[i][1] + bi0.y;
        o.z = acc[i][2] + bi0.z; o.w = acc[i][3] + bi0.w;
        *(float4*)(dst + 0) = o;
        o.x = acc[i][4] + bi1.x; o.y = acc[i][5] + bi1.y;
        o.z = acc[i][6] + bi1.z; o.w = acc[i][7] + bi1.w;
        *(float4*)(dst + 4) = o;
    }
}

// ---------------------------------------------------------------------------
// Local attention. 128 threads: a = tid>>3 -> rows 4a..4a+3, kg = tid&7.
// QK: 4 rows x 8 keys (keys kg+8j).  PV: 4 rows x 8 d-cols (cols kg*8..+7).
// All key tiles 64-aligned -> fully valid or skipped.
// ---------------------------------------------------------------------------
#define ATTN_SMEM_BYTES (4 * 64 * 68 * 4)

__global__ __launch_bounds__(128)
void attn_kernel()
{
    extern __shared__ float sm[];
    float* Qs = sm;
    float* Ks = sm + 64 * 68;
    float* Vs = sm + 2 * 64 * 68;
    float* Ps = sm + 3 * 64 * 68;

    const int tid = threadIdx.x;
    const int a  = tid >> 3;         // 0..15
    const int kg = tid & 7;
    const int rq = 4 * a;            // first of 4 query rows
    const int nchunk = blockIdx.x, h = blockIdx.y, b = blockIdx.z;
    const int chunkStart = nchunk * C_;
    const int base = (b * H_ + h) * S_ * D_;

    // cooperative load map: 64 rows x 64 cols, 32 floats/thread
    const int lrow = tid >> 1;
    const int lcol = (tid & 1) * 32;

    {   // load Q chunk
        const float* src = g_q + base + (chunkStart + lrow) * D_ + lcol;
        float* dst = Qs + lrow * 68 + lcol;
        #pragma unroll
        for (int j = 0; j < 8; j++)
            *(float4*)(dst + 4 * j) = *(const float4*)(src + 4 * j);
    }

    float mrow[4], lsumr[4];
    float acc[4][8];
    #pragma unroll
    for (int i = 0; i < 4; i++) {
        mrow[i] = -INFINITY; lsumr[i] = 0.f;
        #pragma unroll
        for (int j = 0; j < 8; j++) acc[i][j] = 0.f;
    }

    for (int t = 0; t < 9; t++) {
        const int tileStart = chunkStart - R_ + t * C_;
        if (tileStart < 0 || tileStart >= S_) continue;   // uniform per block

        __syncthreads();
        {
            const int pos = tileStart + lrow;
            const float* ksrc = g_k + base + pos * D_ + lcol;
            const float* vsrc = g_v + base + pos * D_ + lcol;
            float* kdst = Ks + lrow * 68 + lcol;
            float* vdst = Vs + lrow * 68 + lcol;
            #pragma unroll
            for (int j = 0; j < 8; j++) {
                *(float4*)(kdst + 4 * j) = *(const float4*)(ksrc + 4 * j);
                *(float4*)(vdst + 4 * j) = *(const float4*)(vsrc + 4 * j);
            }
        }
        __syncthreads();

        // ---- scores: s[i][j] = q(rq+i) . k(kg+8j) ----
        float s[4][8];
        #pragma unroll
        for (int i = 0; i < 4; i++)
            #pragma unroll
            for (int j = 0; j < 8; j++) s[i][j] = 0.f;

        #pragma unroll
        for (int kk = 0; kk < 64; kk += 4) {
            float4 q0 = *(float4*)&Qs[(rq + 0) * 68 + kk];
            float4 q1 = *(float4*)&Qs[(rq + 1) * 68 + kk];
            float4 q2 = *(float4*)&Qs[(rq + 2) * 68 + kk];
            float4 q3 = *(float4*)&Qs[(rq + 3) * 68 + kk];
            #pragma unroll
            for (int j = 0; j < 8; j++) {
                float4 k4 = *(float4*)&Ks[(kg + 8 * j) * 68 + kk];
                s[0][j] += q0.x * k4.x + q0.y * k4.y + q0.z * k4.z + q0.w * k4.w;
                s[1][j] += q1.x * k4.x + q1.y * k4.y + q1.z * k4.z + q1.w * k4.w;
                s[2][j] += q2.x * k4.x + q2.y * k4.y + q2.z * k4.z + q2.w * k4.w;
                s[3][j] += q3.x * k4.x + q3.y * k4.y + q3.z * k4.z + q3.w * k4.w;
            }
        }

        // ---- online softmax per row (reduce over 8 kg lanes) ----
        #pragma unroll
        for (int i = 0; i < 4; i++) {
            float mx = s[i][0];
            #pragma unroll
            for (int j = 1; j < 8; j++) mx = fmaxf(mx, s[i][j]);
            mx = fmaxf(mx, __shfl_xor_sync(0xffffffffu, mx, 1));
            mx = fmaxf(mx, __shfl_xor_sync(0xffffffffu, mx, 2));
            mx = fmaxf(mx, __shfl_xor_sync(0xffffffffu, mx, 4));
            const float mn = fmaxf(mrow[i], mx);
            const float rs = __expf(mrow[i] - mn);
            float ls = 0.f;
            #pragma unroll
            for (int j = 0; j < 8; j++) {
                float p = __expf(s[i][j] - mn);
                Ps[(rq + i) * 68 + kg + 8 * j] = p;
                ls += p;
            }
            ls += __shfl_xor_sync(0xffffffffu, ls, 1);
            ls += __shfl_xor_sync(0xffffffffu, ls, 2);
            ls += __shfl_xor_sync(0xffffffffu, ls, 4);
            lsumr[i] = lsumr[i] * rs + ls;
            mrow[i] = mn;
            #pragma unroll
            for (int j = 0; j < 8; j++) acc[i][j] *= rs;
        }

        __syncwarp();   // P rows of this group written by this warp's 8 lanes

        // ---- PV: acc[i][0..7] += sum_k P[rq+i][k] * V[k][kg*8..+7] ----
        #pragma unroll 4
        for (int k = 0; k < 64; k += 4) {
            float4 p0 = *(float4*)&Ps[(rq + 0) * 68 + k];
            float4 p1 = *(float4*)&Ps[(rq + 1) * 68 + k];
            float4 p2 = *(float4*)&Ps[(rq + 2) * 68 + k];
            float4 p3 = *(float4*)&Ps[(rq + 3) * 68 + k];
            #pragma unroll
            for (int kk2 = 0; kk2 < 4; kk2++) {
                float4 va = *(float4*)&Vs[(k + kk2) * 68 + kg * 8];
                float4 vb = *(float4*)&Vs[(k + kk2) * 68 + kg * 8 + 4];
                const float pv0 = (kk2 == 0) ? p0.x : (kk2 == 1) ? p0.y : (kk2 == 2) ? p0.z : p0.w;
                const float pv1 = (kk2 == 0) ? p1.x : (kk2 == 1) ? p1.y : (kk2 == 2) ? p1.z : p1.w;
                const float pv2 = (kk2 == 0) ? p2.x : (kk2 == 1) ? p2.y : (kk2 == 2) ? p2.z : p2.w;
                const float pv3 = (kk2 == 0) ? p3.x : (kk2 == 1) ? p3.y : (kk2 == 2) ? p3.z : p3.w;
                acc[0][0] += pv0 * va.x; acc[0][1] += pv0 * va.y; acc[0][2] += pv0 * va.z; acc[0][3] += pv0 * va.w;
                acc[0][4] += pv0 * vb.x; acc[0][5] += pv0 * vb.y; acc[0][6] += pv0 * vb.z; acc[0][7] += pv0 * vb.w;
                acc[1][0] += pv1 * va.x; acc[1][1] += pv1 * va.y; acc[1][2] += pv1 * va.z; acc[1][3] += pv1 * va.w;
                acc[1][4] += pv1 * vb.x; acc[1][5] += pv1 * vb.y; acc[1][6] += pv1 * vb.z; acc[1][7] += pv1 * vb.w;
                acc[2][0] += pv2 * va.x; acc[2][1] += pv2 * va.y; acc[2][2] += pv2 * va.z; acc[2][3] += pv2 * va.w;
                acc[2][4] += pv2 * vb.x; acc[2][5] += pv2 * vb.y; acc[2][6] += pv2 * vb.z; acc[2][7] += pv2 * vb.w;
                acc[3][0] += pv3 * va.x; acc[3][1] += pv3 * va.y; acc[3][2] += pv3 * va.z; acc[3][3] += pv3 * va.w;
                acc[3][4] += pv3 * vb.x; acc[3][5] += pv3 * vb.y; acc[3][6] += pv3 * vb.z; acc[3][7] += pv3 * vb.w;
            }
        }
    }

    // ---- write ctx: (b, s, h*64 + d) ----
    const int e0 = h * 64 + kg * 8;
    #pragma unroll
    for (int i = 0; i < 4; i++) {
        const float inv = 1.f / lsumr[i];
        float* dst = g_ctx + (size_t)(b * S_ + chunkStart + rq + i) * E_ + e0;
        float4 o;
        o.x = acc[i][0] * inv; o.y = acc[i][1] * inv;
        o.z = acc[i][2] * inv; o.w = acc[i][3] * inv;
        *(float4*)(dst + 0) = o;
        o.x = acc[i][4] * inv; o.y = acc[i][5] * inv;
        o.z = acc[i][6] * inv; o.w = acc[i][7] * inv;
        *(float4*)(dst + 4) = o;
    }
}

// ---------------------------------------------------------------------------
extern "C" void kernel_launch(void* const* d_in, const int* in_sizes, int n_in,
                              void* d_out, int out_size)
{
    const float* X  = (const float*)d_in[0];
    const float* Wq = (const float*)d_in[1];
    const float* bq = (const float*)d_in[2];
    const float* Wk = (const float*)d_in[3];
    const float* bk = (const float*)d_in[4];
    const float* Wv = (const float*)d_in[5];
    const float* bv = (const float*)d_in[6];
    const float* Wo = (const float*)d_in[7];
    const float* bo = (const float*)d_in[8];
    float* out = (float*)d_out;

    cudaFuncSetAttribute(attn_kernel,
                         cudaFuncAttributeMaxDynamicSharedMemorySize,
                         ATTN_SMEM_BYTES);

    qkv_kernel<<<dim3(18, MTOT / BM), 256>>>(X, Wq, bq, Wk, bk, Wv, bv);

    attn_kernel<<<dim3(S_ / C_, H_, B_), 128, ATTN_SMEM_BYTES>>>();

    proj_kernel<<<dim3(E_ / BN, MTOT / BM), 256>>>(Wo, bo, out);
}

// round 4
// speedup vs baseline: 1.3892x; 1.1154x over previous
#include <cuda_runtime.h>
#include <math.h>

#define B_ 2
#define S_ 4096
#define E_ 768
#define H_ 12
#define D_ 64
#define C_ 64
#define R_ 256
#define MTOT (B_*S_)

__device__ float g_q[B_*H_*S_*D_];
__device__ float g_k[B_*H_*S_*D_];
__device__ float g_v[B_*H_*S_*D_];
__device__ float g_ctx[MTOT*E_];

#define BM 128
#define BN 128
#define BKK 16

// ---------------------------------------------------------------------------
// SGEMM core: 128x128x16, 256 threads, split 8x8 micro-tile (4+4 rows/cols,
// halves 64 apart) so every LDS.128 is lane-contiguous. Double-buffered smem.
// ---------------------------------------------------------------------------

// qkv fused: grid.x = 18 (z = matrix, 6 n-tiles each), grid.y = 64 m-tiles.
__global__ __launch_bounds__(256)
void qkv_kernel(const float* __restrict__ X,
                const float* __restrict__ Wq, const float* __restrict__ bq,
                const float* __restrict__ Wk, const float* __restrict__ bk,
                const float* __restrict__ Wv, const float* __restrict__ bv)
{
    __shared__ float As[2][BKK][BM + 4];
    __shared__ float Bs[2][BKK][BN];

    const int z    = blockIdx.x / 6;
    const int nblk = blockIdx.x % 6;
    const float* __restrict__ W    = (z == 0) ? Wq : (z == 1) ? Wk : Wv;
    const float* __restrict__ bias = (z == 0) ? bq : (z == 1) ? bk : bv;
    float* out = (z == 0) ? g_q : (z == 1) ? g_k : g_v;
    const float scale = (z == 0) ? 0.125f : 1.0f;

    const int tid = threadIdx.x;
    const int tx = tid & 15, ty = tid >> 4;
    const int m0 = blockIdx.y * BM, n0 = nblk * BN;

    const int ar = tid >> 1, ac = (tid & 1) * 8;
    const int br = tid >> 4, bc = (tid & 15) * 8;

    const float* aPtr = X + (size_t)(m0 + ar) * E_ + ac;
    const float* bPtr = W + (size_t)br * E_ + n0 + bc;

    float4 a0 = *(const float4*)(aPtr + 0);
    float4 a1 = *(const float4*)(aPtr + 4);
    float4 b0 = *(const float4*)(bPtr + 0);
    float4 b1 = *(const float4*)(bPtr + 4);

    // prologue: fill buffer 0
    As[0][ac + 0][ar] = a0.x; As[0][ac + 1][ar] = a0.y;
    As[0][ac + 2][ar] = a0.z; As[0][ac + 3][ar] = a0.w;
    As[0][ac + 4][ar] = a1.x; As[0][ac + 5][ar] = a1.y;
    As[0][ac + 6][ar] = a1.z; As[0][ac + 7][ar] = a1.w;
    *(float4*)&Bs[0][br][bc + 0] = b0;
    *(float4*)&Bs[0][br][bc + 4] = b1;
    __syncthreads();

    float acc[8][8] = {};
    int p = 0;

    for (int k0 = 0; k0 < E_; k0 += BKK) {
        const bool hasNext = (k0 + BKK) < E_;
        if (hasNext) {
            a0 = *(const float4*)(aPtr + k0 + BKK + 0);
            a1 = *(const float4*)(aPtr + k0 + BKK + 4);
            b0 = *(const float4*)(bPtr + (size_t)(k0 + BKK) * E_ + 0);
            b1 = *(const float4*)(bPtr + (size_t)(k0 + BKK) * E_ + 4);
        }
        #pragma unroll
        for (int kk = 0; kk < BKK; kk++) {
            float4 alo = *(float4*)&As[p][kk][ty * 4];
            float4 ahi = *(float4*)&As[p][kk][64 + ty * 4];
            float4 blo = *(float4*)&Bs[p][kk][tx * 4];
            float4 bhi = *(float4*)&Bs[p][kk][64 + tx * 4];
            float av[8] = {alo.x, alo.y, alo.z, alo.w, ahi.x, ahi.y, ahi.z, ahi.w};
            float bw[8] = {blo.x, blo.y, blo.z, blo.w, bhi.x, bhi.y, bhi.z, bhi.w};
            #pragma unroll
            for (int i = 0; i < 8; i++)
                #pragma unroll
                for (int j = 0; j < 8; j++)
                    acc[i][j] += av[i] * bw[j];
        }
        if (hasNext) {
            const int q = p ^ 1;
            As[q][ac + 0][ar] = a0.x; As[q][ac + 1][ar] = a0.y;
            As[q][ac + 2][ar] = a0.z; As[q][ac + 3][ar] = a0.w;
            As[q][ac + 4][ar] = a1.x; As[q][ac + 5][ar] = a1.y;
            As[q][ac + 6][ar] = a1.z; As[q][ac + 7][ar] = a1.w;
            *(float4*)&Bs[q][br][bc + 0] = b0;
            *(float4*)&Bs[q][br][bc + 4] = b1;
            __syncthreads();
            p = q;
        }
    }

    // epilogue: remap to (b,h,s,d); col groups at n0+tx*4 and n0+64+tx*4
    const int nA = n0 + tx * 4;
    const int nB = n0 + 64 + tx * 4;
    const int hhA = nA >> 6, dA = nA & 63;
    const int hhB = nB >> 6, dB = nB & 63;
    const float4 biA = *(const float4*)&bias[nA];
    const float4 biB = *(const float4*)&bias[nB];
    #pragma unroll
    for (int i = 0; i < 8; i++) {
        const int m  = m0 + ((i < 4) ? (ty * 4 + i) : (64 + ty * 4 + i - 4));
        const int bb = m >> 12;
        const int s  = m & (S_ - 1);
        float4 o;
        o.x = (acc[i][0] + biA.x) * scale; o.y = (acc[i][1] + biA.y) * scale;
        o.z = (acc[i][2] + biA.z) * scale; o.w = (acc[i][3] + biA.w) * scale;
        *(float4*)&out[((size_t)(bb * H_ + hhA) * S_ + s) * D_ + dA] = o;
        o.x = (acc[i][4] + biB.x) * scale; o.y = (acc[i][5] + biB.y) * scale;
        o.z = (acc[i][6] + biB.z) * scale; o.w = (acc[i][7] + biB.w) * scale;
        *(float4*)&out[((size_t)(bb * H_ + hhB) * S_ + s) * D_ + dB] = o;
    }
}

__global__ __launch_bounds__(256)
void proj_kernel(const float* __restrict__ Wo, const float* __restrict__ bo,
                 float* __restrict__ out)
{
    __shared__ float As[2][BKK][BM + 4];
    __shared__ float Bs[2][BKK][BN];

    const float* __restrict__ X = g_ctx;

    const int tid = threadIdx.x;
    const int tx = tid & 15, ty = tid >> 4;
    const int m0 = blockIdx.y * BM, n0 = blockIdx.x * BN;

    const int ar = tid >> 1, ac = (tid & 1) * 8;
    const int br = tid >> 4, bc = (tid & 15) * 8;

    const float* aPtr = X + (size_t)(m0 + ar) * E_ + ac;
    const float* bPtr = Wo + (size_t)br * E_ + n0 + bc;

    float4 a0 = *(const float4*)(aPtr + 0);
    float4 a1 = *(const float4*)(aPtr + 4);
    float4 b0 = *(const float4*)(bPtr + 0);
    float4 b1 = *(const float4*)(bPtr + 4);

    As[0][ac + 0][ar] = a0.x; As[0][ac + 1][ar] = a0.y;
    As[0][ac + 2][ar] = a0.z; As[0][ac + 3][ar] = a0.w;
    As[0][ac + 4][ar] = a1.x; As[0][ac + 5][ar] = a1.y;
    As[0][ac + 6][ar] = a1.z; As[0][ac + 7][ar] = a1.w;
    *(float4*)&Bs[0][br][bc + 0] = b0;
    *(float4*)&Bs[0][br][bc + 4] = b1;
    __syncthreads();

    float acc[8][8] = {};
    int p = 0;

    for (int k0 = 0; k0 < E_; k0 += BKK) {
        const bool hasNext = (k0 + BKK) < E_;
        if (hasNext) {
            a0 = *(const float4*)(aPtr + k0 + BKK + 0);
            a1 = *(const float4*)(aPtr + k0 + BKK + 4);
            b0 = *(const float4*)(bPtr + (size_t)(k0 + BKK) * E_ + 0);
            b1 = *(const float4*)(bPtr + (size_t)(k0 + BKK) * E_ + 4);
        }
        #pragma unroll
        for (int kk = 0; kk < BKK; kk++) {
            float4 alo = *(float4*)&As[p][kk][ty * 4];
            float4 ahi = *(float4*)&As[p][kk][64 + ty * 4];
            float4 blo = *(float4*)&Bs[p][kk][tx * 4];
            float4 bhi = *(float4*)&Bs[p][kk][64 + tx * 4];
            float av[8] = {alo.x, alo.y, alo.z, alo.w, ahi.x, ahi.y, ahi.z, ahi.w};
            float bw[8] = {blo.x, blo.y, blo.z, blo.w, bhi.x, bhi.y, bhi.z, bhi.w};
            #pragma unroll
            for (int i = 0; i < 8; i++)
                #pragma unroll
                for (int j = 0; j < 8; j++)
                    acc[i][j] += av[i] * bw[j];
        }
        if (hasNext) {
            const int q = p ^ 1;
            As[q][ac + 0][ar] = a0.x; As[q][ac + 1][ar] = a0.y;
            As[q][ac + 2][ar] = a0.z; As[q][ac + 3][ar] = a0.w;
            As[q][ac + 4][ar] = a1.x; As[q][ac + 5][ar] = a1.y;
            As[q][ac + 6][ar] = a1.z; As[q][ac + 7][ar] = a1.w;
            *(float4*)&Bs[q][br][bc + 0] = b0;
            *(float4*)&Bs[q][br][bc + 4] = b1;
            __syncthreads();
            p = q;
        }
    }

    const int nA = n0 + tx * 4;
    const int nB = n0 + 64 + tx * 4;
    const float4 biA = *(const float4*)&bo[nA];
    const float4 biB = *(const float4*)&bo[nB];
    #pragma unroll
    for (int i = 0; i < 8; i++) {
        const int m = m0 + ((i < 4) ? (ty * 4 + i) : (64 + ty * 4 + i - 4));
        float4 o;
        o.x = acc[i][0] + biA.x; o.y = acc[i][1] + biA.y;
        o.z = acc[i][2] + biA.z; o.w = acc[i][3] + biA.w;
        *(float4*)&out[(size_t)m * E_ + nA] = o;
        o.x = acc[i][4] + biB.x; o.y = acc[i][5] + biB.y;
        o.z = acc[i][6] + biB.z; o.w = acc[i][7] + biB.w;
        *(float4*)&out[(size_t)m * E_ + nB] = o;
    }
}

// ---------------------------------------------------------------------------
// Local attention. 128 threads: a = tid>>3 -> rows 4a..4a+3, kg = tid&7.
// QK: 4 rows x 8 keys (kg+8j).  PV: 4 rows x 8 d-cols split {kg*4, 32+kg*4}
// so V LDS.128s are lane-contiguous (1 wavefront each).
// ---------------------------------------------------------------------------
#define ATTN_SMEM_BYTES (4 * 64 * 68 * 4)

__global__ __launch_bounds__(128)
void attn_kernel()
{
    extern __shared__ float sm[];
    float* Qs = sm;
    float* Ks = sm + 64 * 68;
    float* Vs = sm + 2 * 64 * 68;
    float* Ps = sm + 3 * 64 * 68;

    const int tid = threadIdx.x;
    const int a  = tid >> 3;
    const int kg = tid & 7;
    const int rq = 4 * a;
    const int nchunk = blockIdx.x, h = blockIdx.y, b = blockIdx.z;
    const int chunkStart = nchunk * C_;
    const int base = (b * H_ + h) * S_ * D_;

    const int lrow = tid >> 1;
    const int lcol = (tid & 1) * 32;

    {
        const float* src = g_q + base + (chunkStart + lrow) * D_ + lcol;
        float* dst = Qs + lrow * 68 + lcol;
        #pragma unroll
        for (int j = 0; j < 8; j++)
            *(float4*)(dst + 4 * j) = *(const float4*)(src + 4 * j);
    }

    float mrow[4], lsumr[4];
    float acc[4][8];
    #pragma unroll
    for (int i = 0; i < 4; i++) {
        mrow[i] = -INFINITY; lsumr[i] = 0.f;
        #pragma unroll
        for (int j = 0; j < 8; j++) acc[i][j] = 0.f;
    }

    for (int t = 0; t < 9; t++) {
        const int tileStart = chunkStart - R_ + t * C_;
        if (tileStart < 0 || tileStart >= S_) continue;

        __syncthreads();
        {
            const int pos = tileStart + lrow;
            const float* ksrc = g_k + base + pos * D_ + lcol;
            const float* vsrc = g_v + base + pos * D_ + lcol;
            float* kdst = Ks + lrow * 68 + lcol;
            float* vdst = Vs + lrow * 68 + lcol;
            #pragma unroll
            for (int j = 0; j < 8; j++) {
                *(float4*)(kdst + 4 * j) = *(const float4*)(ksrc + 4 * j);
                *(float4*)(vdst + 4 * j) = *(const float4*)(vsrc + 4 * j);
            }
        }
        __syncthreads();

        float s[4][8];
        #pragma unroll
        for (int i = 0; i < 4; i++)
            #pragma unroll
            for (int j = 0; j < 8; j++) s[i][j] = 0.f;

        #pragma unroll
        for (int kk = 0; kk < 64; kk += 4) {
            float4 q0 = *(float4*)&Qs[(rq + 0) * 68 + kk];
            float4 q1 = *(float4*)&Qs[(rq + 1) * 68 + kk];
            float4 q2 = *(float4*)&Qs[(rq + 2) * 68 + kk];
            float4 q3 = *(float4*)&Qs[(rq + 3) * 68 + kk];
            #pragma unroll
            for (int j = 0; j < 8; j++) {
                float4 k4 = *(float4*)&Ks[(kg + 8 * j) * 68 + kk];
                s[0][j] += q0.x * k4.x + q0.y * k4.y + q0.z * k4.z + q0.w * k4.w;
                s[1][j] += q1.x * k4.x + q1.y * k4.y + q1.z * k4.z + q1.w * k4.w;
                s[2][j] += q2.x * k4.x + q2.y * k4.y + q2.z * k4.z + q2.w * k4.w;
                s[3][j] += q3.x * k4.x + q3.y * k4.y + q3.z * k4.z + q3.w * k4.w;
            }
        }

        #pragma unroll
        for (int i = 0; i < 4; i++) {
            float mx = s[i][0];
            #pragma unroll
            for (int j = 1; j < 8; j++) mx = fmaxf(mx, s[i][j]);
            mx = fmaxf(mx, __shfl_xor_sync(0xffffffffu, mx, 1));
            mx = fmaxf(mx, __shfl_xor_sync(0xffffffffu, mx, 2));
            mx = fmaxf(mx, __shfl_xor_sync(0xffffffffu, mx, 4));
            const float mn = fmaxf(mrow[i], mx);
            const float rs = __expf(mrow[i] - mn);
            float ls = 0.f;
            #pragma unroll
            for (int j = 0; j < 8; j++) {
                float pv = __expf(s[i][j] - mn);
                Ps[(rq + i) * 68 + kg + 8 * j] = pv;
                ls += pv;
            }
            ls += __shfl_xor_sync(0xffffffffu, ls, 1);
            ls += __shfl_xor_sync(0xffffffffu, ls, 2);
            ls += __shfl_xor_sync(0xffffffffu, ls, 4);
            lsumr[i] = lsumr[i] * rs + ls;
            mrow[i] = mn;
            #pragma unroll
            for (int j = 0; j < 8; j++) acc[i][j] *= rs;
        }

        __syncwarp();

        // PV: cols kg*4..+3 (acc[.][0..3]) and 32+kg*4..+3 (acc[.][4..7])
        #pragma unroll 4
        for (int k = 0; k < 64; k += 4) {
            float4 p0 = *(float4*)&Ps[(rq + 0) * 68 + k];
            float4 p1 = *(float4*)&Ps[(rq + 1) * 68 + k];
            float4 p2 = *(float4*)&Ps[(rq + 2) * 68 + k];
            float4 p3 = *(float4*)&Ps[(rq + 3) * 68 + k];
            #pragma unroll
            for (int kk2 = 0; kk2 < 4; kk2++) {
                float4 va = *(float4*)&Vs[(k + kk2) * 68 + kg * 4];
                float4 vb = *(float4*)&Vs[(k + kk2) * 68 + 32 + kg * 4];
                const float pv0 = (kk2 == 0) ? p0.x : (kk2 == 1) ? p0.y : (kk2 == 2) ? p0.z : p0.w;
                const float pv1 = (kk2 == 0) ? p1.x : (kk2 == 1) ? p1.y : (kk2 == 2) ? p1.z : p1.w;
                const float pv2 = (kk2 == 0) ? p2.x : (kk2 == 1) ? p2.y : (kk2 == 2) ? p2.z : p2.w;
                const float pv3 = (kk2 == 0) ? p3.x : (kk2 == 1) ? p3.y : (kk2 == 2) ? p3.z : p3.w;
                acc[0][0] += pv0 * va.x; acc[0][1] += pv0 * va.y; acc[0][2] += pv0 * va.z; acc[0][3] += pv0 * va.w;
                acc[0][4] += pv0 * vb.x; acc[0][5] += pv0 * vb.y; acc[0][6] += pv0 * vb.z; acc[0][7] += pv0 * vb.w;
                acc[1][0] += pv1 * va.x; acc[1][1] += pv1 * va.y; acc[1][2] += pv1 * va.z; acc[1][3] += pv1 * va.w;
                acc[1][4] += pv1 * vb.x; acc[1][5] += pv1 * vb.y; acc[1][6] += pv1 * vb.z; acc[1][7] += pv1 * vb.w;
                acc[2][0] += pv2 * va.x; acc[2][1] += pv2 * va.y; acc[2][2] += pv2 * va.z; acc[2][3] += pv2 * va.w;
                acc[2][4] += pv2 * vb.x; acc[2][5] += pv2 * vb.y; acc[2][6] += pv2 * vb.z; acc[2][7] += pv2 * vb.w;
                acc[3][0] += pv3 * va.x; acc[3][1] += pv3 * va.y; acc[3][2] += pv3 * va.z; acc[3][3] += pv3 * va.w;
                acc[3][4] += pv3 * vb.x; acc[3][5] += pv3 * vb.y; acc[3][6] += pv3 * vb.z; acc[3][7] += pv3 * vb.w;
            }
        }
    }

    // write ctx: (b, s, h*64 + d); d groups kg*4 and 32+kg*4
    const int eA = h * 64 + kg * 4;
    const int eB = h * 64 + 32 + kg * 4;
    #pragma unroll
    for (int i = 0; i < 4; i++) {
        const float inv = 1.f / lsumr[i];
        float* dstbase = g_ctx + (size_t)(b * S_ + chunkStart + rq + i) * E_;
        float4 o;
        o.x = acc[i][0] * inv; o.y = acc[i][1] * inv;
        o.z = acc[i][2] * inv; o.w = acc[i][3] * inv;
        *(float4*)(dstbase + eA) = o;
        o.x = acc[i][4] * inv; o.y = acc[i][5] * inv;
        o.z = acc[i][6] * inv; o.w = acc[i][7] * inv;
        *(float4*)(dstbase + eB) = o;
    }
}

// ---------------------------------------------------------------------------
extern "C" void kernel_launch(void* const* d_in, const int* in_sizes, int n_in,
                              void* d_out, int out_size)
{
    const float* X  = (const float*)d_in[0];
    const float* Wq = (const float*)d_in[1];
    const float* bq = (const float*)d_in[2];
    const float* Wk = (const float*)d_in[3];
    const float* bk = (const float*)d_in[4];
    const float* Wv = (const float*)d_in[5];
    const float* bv = (const float*)d_in[6];
    const float* Wo = (const float*)d_in[7];
    const float* bo = (const float*)d_in[8];
    float* out = (float*)d_out;

    cudaFuncSetAttribute(attn_kernel,
                         cudaFuncAttributeMaxDynamicSharedMemorySize,
                         ATTN_SMEM_BYTES);

    qkv_kernel<<<dim3(18, MTOT / BM), 256>>>(X, Wq, bq, Wk, bk, Wv, bv);

    attn_kernel<<<dim3(S_ / C_, H_, B_), 128, ATTN_SMEM_BYTES>>>();

    proj_kernel<<<dim3(E_ / BN, MTOT / BM), 256>>>(Wo, bo, out);
}

// round 6
// speedup vs baseline: 2.1758x; 1.5663x over previous
#include <cuda_runtime.h>
#include <cuda_bf16.h>
#include <math.h>
#include <stdint.h>

#define B_ 2
#define S_ 4096
#define E_ 768
#define H_ 12
#define D_ 64
#define C_ 64
#define R_ 256
#define MTOT (B_*S_)

// fp32 q/k/v for the attention kernel
__device__ float g_q[B_*H_*S_*D_];
__device__ float g_k[B_*H_*S_*D_];
__device__ float g_v[B_*H_*S_*D_];
// bf16 split operands for tensor-core GEMMs
__device__ __nv_bfloat16 g_xhi[MTOT*E_];
__device__ __nv_bfloat16 g_xlo[MTOT*E_];
__device__ __nv_bfloat16 g_wt_hi[4*E_*E_];   // [z*768+n][k]: Wq^T,Wk^T,Wv^T,Wo^T
__device__ __nv_bfloat16 g_wt_lo[4*E_*E_];
__device__ __nv_bfloat16 g_chi[MTOT*E_];     // ctx hi/lo (written by attn)
__device__ __nv_bfloat16 g_clo[MTOT*E_];

// ---------------------------------------------------------------------------
// helpers
// ---------------------------------------------------------------------------
__device__ __forceinline__ uint32_t smem_u32(const void* p) {
    uint32_t a;
    asm("{ .reg .u64 t; cvta.to.shared.u64 t, %1; cvt.u32.u64 %0, t; }" : "=r"(a) : "l"(p));
    return a;
}
#define SWZ(off) ((off) ^ (((off) >> 3) & 0x70))

#define CP16(dst, src) \
    asm volatile("cp.async.cg.shared.global [%0], [%1], 16;" :: "r"(dst), "l"(src) : "memory")
#define CP_COMMIT() asm volatile("cp.async.commit_group;" ::: "memory")
#define CP_WAIT1()  asm volatile("cp.async.wait_group 1;" ::: "memory")
#define CP_WAIT0()  asm volatile("cp.async.wait_group 0;" ::: "memory")

#define LDMX4(r0, r1, r2, r3, a) \
    asm volatile("ldmatrix.sync.aligned.m8n8.x4.shared.b16 {%0,%1,%2,%3}, [%4];" \
                 : "=r"(r0), "=r"(r1), "=r"(r2), "=r"(r3) : "r"(a))

#define MMA_BF16(d, a, b) \
    asm volatile("mma.sync.aligned.m16n8k16.row.col.f32.bf16.bf16.f32 " \
                 "{%0,%1,%2,%3}, {%4,%5,%6,%7}, {%8,%9}, {%0,%1,%2,%3};" \
                 : "+f"((d)[0]), "+f"((d)[1]), "+f"((d)[2]), "+f"((d)[3]) \
                 : "r"((a)[0]), "r"((a)[1]), "r"((a)[2]), "r"((a)[3]), \
                   "r"((b)[0]), "r"((b)[1]))

__device__ __forceinline__ uint32_t packbf2(float lo, float hi) {
    uint32_t r;
    asm("cvt.rn.bf16x2.f32 %0, %1, %2;" : "=r"(r) : "f"(hi), "f"(lo));
    return r;
}
__device__ __forceinline__ float bfres(float x) {
    return x - __bfloat162float(__float2bfloat16(x));
}

// ---------------------------------------------------------------------------
// prep kernels
// ---------------------------------------------------------------------------
__global__ __launch_bounds__(256)
void convert_x(const float* __restrict__ X)
{
    size_t i = ((size_t)blockIdx.x * 256 + threadIdx.x) * 4;
    float4 v = *(const float4*)(X + i);
    uint2 hi, lo;
    hi.x = packbf2(v.x, v.y); hi.y = packbf2(v.z, v.w);
    lo.x = packbf2(bfres(v.x), bfres(v.y));
    lo.y = packbf2(bfres(v.z), bfres(v.w));
    *(uint2*)&g_xhi[i] = hi;
    *(uint2*)&g_xlo[i] = lo;
}

__global__ __launch_bounds__(256)
void transpose_w(const float* __restrict__ Wq, const float* __restrict__ Wk,
                 const float* __restrict__ Wv, const float* __restrict__ Wo)
{
    __shared__ float st[32][33];
    const int z = blockIdx.z;
    const float* __restrict__ W = (z == 0) ? Wq : (z == 1) ? Wk : (z == 2) ? Wv : Wo;
    const int n0 = blockIdx.x * 32, k0 = blockIdx.y * 32;
    const int tx = threadIdx.x, ty = threadIdx.y;
    #pragma unroll
    for (int j = 0; j < 4; j++)
        st[ty + 8 * j][tx] = W[(size_t)(k0 + ty + 8 * j) * E_ + n0 + tx];
    __syncthreads();
    #pragma unroll
    for (int j = 0; j < 4; j++) {
        float v = st[tx][ty + 8 * j];
        size_t dst = (size_t)(z * E_ + n0 + ty + 8 * j) * E_ + k0 + tx;
        __nv_bfloat16 h = __float2bfloat16(v);
        g_wt_hi[dst] = h;
        g_wt_lo[dst] = __float2bfloat16(v - __bfloat162float(h));
    }
}

// ---------------------------------------------------------------------------
// mma.sync GEMM: C[128x128] = A[128x768] * B^T with bf16 hi/lo split.
// 256 threads, warps 2(m) x 4(n), warp tile 64x32, K-chunk 64, cp.async
// double buffer. Smem per buffer: Ah|Al|Bh|Bl each 128x64 bf16 (16KB).
// ---------------------------------------------------------------------------
#define BKC 64
#define NCH (E_/BKC)            // 12
#define BUFB 65536
#define GEMM_SMEM (2*BUFB)      // 131072

__global__ __launch_bounds__(256)
void gemm_mma(int qkvmode,
              const float* __restrict__ bias0, const float* __restrict__ bias1,
              const float* __restrict__ bias2, float* __restrict__ outp)
{
    extern __shared__ char smem[];
    const uint32_t sb = smem_u32(smem);
    const int tid = threadIdx.x;
    const int wid = tid >> 5, lane = tid & 31;
    const int wm = wid >> 2, wn = wid & 3;   // 2 x 4 warp grid
    const int m0 = blockIdx.y * 128, n0 = blockIdx.x * 128;

    const __nv_bfloat16* __restrict__ Ah = qkvmode ? g_xhi : g_chi;
    const __nv_bfloat16* __restrict__ Al = qkvmode ? g_xlo : g_clo;
    const __nv_bfloat16* __restrict__ Bh = g_wt_hi + (qkvmode ? 0 : (size_t)2304 * E_);
    const __nv_bfloat16* __restrict__ Bl = g_wt_lo + (qkvmode ? 0 : (size_t)2304 * E_);

    // cp.async mapping: unit u = tid + 256*it -> row u>>3, 16B-unit u&7
    const int crow[4] = { (tid + 0) >> 3, (tid + 256) >> 3, (tid + 512) >> 3, (tid + 768) >> 3 };
    const int ccu [4] = { tid & 7, tid & 7, tid & 7, tid & 7 };

    float acc[4][4][4];
    #pragma unroll
    for (int i = 0; i < 4; i++)
        #pragma unroll
        for (int j = 0; j < 4; j++)
            #pragma unroll
            for (int q = 0; q < 4; q++) acc[i][j][q] = 0.f;

    // issue cp.async for chunk c into buffer b
    auto issue = [&](int c, int b) {
        const uint32_t bo = sb + b * BUFB;
        #pragma unroll
        for (int it = 0; it < 4; it++) {
            const int row = crow[it], cu = ccu[it];
            const size_t ga = (size_t)(m0 + row) * E_ + c * BKC + cu * 8;
            const size_t gb = (size_t)(n0 + row) * E_ + c * BKC + cu * 8;
            const uint32_t so = SWZ((uint32_t)(row * 128 + cu * 16));
            CP16(bo + 0     + so, Ah + ga);
            CP16(bo + 16384 + so, Al + ga);
            CP16(bo + 32768 + so, Bh + gb);
            CP16(bo + 49152 + so, Bl + gb);
        }
        CP_COMMIT();
    };

    issue(0, 0);

    // ldmatrix row/unit params (constant per thread)
    const int arow = (lane & 15);            // + wm*64 + mt*16
    const int au   = (lane >> 4);            // + ks*2
    const int brow = ((lane >> 4) << 3) + (lane & 7);  // + wn*32 + half*16
    const int bu   = ((lane >> 3) & 1);      // + ks*2

    for (int c = 0; c < NCH; c++) {
        if (c + 1 < NCH) { issue(c + 1, (c + 1) & 1); CP_WAIT1(); }
        else             { CP_WAIT0(); }
        __syncthreads();

        const uint32_t bo = sb + (c & 1) * BUFB;
        const uint32_t sAh = bo, sAl = bo + 16384, sBh = bo + 32768, sBl = bo + 49152;

        #pragma unroll
        for (int ks = 0; ks < 4; ks++) {
            uint32_t ah[4][4], al[4][4], bh[4][2], bl[4][2];
            #pragma unroll
            for (int mt = 0; mt < 4; mt++) {
                const int r = wm * 64 + mt * 16 + arow;
                const int u = ks * 2 + au;
                const uint32_t off = r * 128 + ((u ^ (r & 7)) << 4);
                LDMX4(ah[mt][0], ah[mt][1], ah[mt][2], ah[mt][3], sAh + off);
                LDMX4(al[mt][0], al[mt][1], al[mt][2], al[mt][3], sAl + off);
            }
            #pragma unroll
            for (int half = 0; half < 2; half++) {
                const int r = wn * 32 + half * 16 + brow;
                const int u = ks * 2 + bu;
                const uint32_t off = r * 128 + ((u ^ (r & 7)) << 4);
                LDMX4(bh[half*2][0], bh[half*2][1], bh[half*2+1][0], bh[half*2+1][1], sBh + off);
                LDMX4(bl[half*2][0], bl[half*2][1], bl[half*2+1][0], bl[half*2+1][1], sBl + off);
            }
            #pragma unroll
            for (int mi = 0; mi < 4; mi++)
                #pragma unroll
                for (int ni = 0; ni < 4; ni++) {
                    MMA_BF16(acc[mi][ni], ah[mi], bh[ni]);
                    MMA_BF16(acc[mi][ni], ah[mi], bl[ni]);
                    MMA_BF16(acc[mi][ni], al[mi], bh[ni]);
                }
        }
        __syncthreads();   // all warps done with this buffer before it is refilled
    }

    // ---- epilogue: direct stores with bias / layout remap ----
    const int g = lane >> 2, tig = lane & 3;
    #pragma unroll
    for (int ni = 0; ni < 4; ni++) {
        const int col = n0 + wn * 32 + ni * 8 + 2 * tig;
        if (qkvmode) {
            const int z = (col >= 1536) ? 2 : (col >= 768) ? 1 : 0;
            const int n_in = col - z * 768;
            const float* bias = (z == 0) ? bias0 : (z == 1) ? bias1 : bias2;
            const float2 bi = *(const float2*)&bias[n_in];
            const float scale = (z == 0) ? 0.125f : 1.0f;
            float* dstArr = (z == 0) ? g_q : (z == 1) ? g_k : g_v;
            const int h = n_in >> 6, d = n_in & 63;
            #pragma unroll
            for (int mi = 0; mi < 4; mi++) {
                #pragma unroll
                for (int hf = 0; hf < 2; hf++) {
                    const int row = m0 + wm * 64 + mi * 16 + g + hf * 8;
                    const int bb = row >> 12, s = row & (S_ - 1);
                    float2 o;
                    o.x = (acc[mi][ni][hf*2+0] + bi.x) * scale;
                    o.y = (acc[mi][ni][hf*2+1] + bi.y) * scale;
                    *(float2*)&dstArr[((size_t)(bb * H_ + h) * S_ + s) * D_ + d] = o;
                }
            }
        } else {
            const float2 bi = *(const float2*)&bias0[col];
            #pragma unroll
            for (int mi = 0; mi < 4; mi++) {
                #pragma unroll
                for (int hf = 0; hf < 2; hf++) {
                    const int row = m0 + wm * 64 + mi * 16 + g + hf * 8;
                    float2 o;
                    o.x = acc[mi][ni][hf*2+0] + bi.x;
                    o.y = acc[mi][ni][hf*2+1] + bi.y;
                    *(float2*)&outp[(size_t)row * E_ + col] = o;
                }
            }
        }
    }
}

// ---------------------------------------------------------------------------
// Local attention (fp32). Epilogue writes ctx as bf16 hi/lo.
// ---------------------------------------------------------------------------
#define ATTN_SMEM_BYTES (4 * 64 * 68 * 4)

__device__ __forceinline__ void store4split(float x0, float x1, float x2, float x3, size_t idx)
{
    uint2 hi, lo;
    hi.x = packbf2(x0, x1); hi.y = packbf2(x2, x3);
    lo.x = packbf2(bfres(x0), bfres(x1));
    lo.y = packbf2(bfres(x2), bfres(x3));
    *(uint2*)&g_chi[idx] = hi;
    *(uint2*)&g_clo[idx] = lo;
}

__global__ __launch_bounds__(128)
void attn_kernel()
{
    extern __shared__ float sm[];
    float* Qs = sm;
    float* Ks = sm + 64 * 68;
    float* Vs = sm + 2 * 64 * 68;
    float* Ps = sm + 3 * 64 * 68;

    const int tid = threadIdx.x;
    const int a  = tid >> 3;
    const int kg = tid & 7;
    const int rq = 4 * a;
    const int nchunk = blockIdx.x, h = blockIdx.y, b = blockIdx.z;
    const int chunkStart = nchunk * C_;
    const int base = (b * H_ + h) * S_ * D_;

    const int lrow = tid >> 1;
    const int lcol = (tid & 1) * 32;

    {
        const float* src = g_q + base + (chunkStart + lrow) * D_ + lcol;
        float* dst = Qs + lrow * 68 + lcol;
        #pragma unroll
        for (int j = 0; j < 8; j++)
            *(float4*)(dst + 4 * j) = *(const float4*)(src + 4 * j);
    }

    float mrow[4], lsumr[4];
    float acc[4][8];
    #pragma unroll
    for (int i = 0; i < 4; i++) {
        mrow[i] = -INFINITY; lsumr[i] = 0.f;
        #pragma unroll
        for (int j = 0; j < 8; j++) acc[i][j] = 0.f;
    }

    for (int t = 0; t < 9; t++) {
        const int tileStart = chunkStart - R_ + t * C_;
        if (tileStart < 0 || tileStart >= S_) continue;

        __syncthreads();
        {
            const int pos = tileStart + lrow;
            const float* ksrc = g_k + base + pos * D_ + lcol;
            const float* vsrc = g_v + base + pos * D_ + lcol;
            float* kdst = Ks + lrow * 68 + lcol;
            float* vdst = Vs + lrow * 68 + lcol;
            #pragma unroll
            for (int j = 0; j < 8; j++) {
                *(float4*)(kdst + 4 * j) = *(const float4*)(ksrc + 4 * j);
                *(float4*)(vdst + 4 * j) = *(const float4*)(vsrc + 4 * j);
            }
        }
        __syncthreads();

        float s[4][8];
        #pragma unroll
        for (int i = 0; i < 4; i++)
            #pragma unroll
            for (int j = 0; j < 8; j++) s[i][j] = 0.f;

        #pragma unroll
        for (int kk = 0; kk < 64; kk += 4) {
            float4 q0 = *(float4*)&Qs[(rq + 0) * 68 + kk];
            float4 q1 = *(float4*)&Qs[(rq + 1) * 68 + kk];
            float4 q2 = *(float4*)&Qs[(rq + 2) * 68 + kk];
            float4 q3 = *(float4*)&Qs[(rq + 3) * 68 + kk];
            #pragma unroll
            for (int j = 0; j < 8; j++) {
                float4 k4 = *(float4*)&Ks[(kg + 8 * j) * 68 + kk];
                s[0][j] += q0.x * k4.x + q0.y * k4.y + q0.z * k4.z + q0.w * k4.w;
                s[1][j] += q1.x * k4.x + q1.y * k4.y + q1.z * k4.z + q1.w * k4.w;
                s[2][j] += q2.x * k4.x + q2.y * k4.y + q2.z * k4.z + q2.w * k4.w;
                s[3][j] += q3.x * k4.x + q3.y * k4.y + q3.z * k4.z + q3.w * k4.w;
            }
        }

        #pragma unroll
        for (int i = 0; i < 4; i++) {
            float mx = s[i][0];
            #pragma unroll
            for (int j = 1; j < 8; j++) mx = fmaxf(mx, s[i][j]);
            mx = fmaxf(mx, __shfl_xor_sync(0xffffffffu, mx, 1));
            mx = fmaxf(mx, __shfl_xor_sync(0xffffffffu, mx, 2));
            mx = fmaxf(mx, __shfl_xor_sync(0xffffffffu, mx, 4));
            const float mn = fmaxf(mrow[i], mx);
            const float rs = __expf(mrow[i] - mn);
            float ls = 0.f;
            #pragma unroll
            for (int j = 0; j < 8; j++) {
                float pv = __expf(s[i][j] - mn);
                Ps[(rq + i) * 68 + kg + 8 * j] = pv;
                ls += pv;
            }
            ls += __shfl_xor_sync(0xffffffffu, ls, 1);
            ls += __shfl_xor_sync(0xffffffffu, ls, 2);
            ls += __shfl_xor_sync(0xffffffffu, ls, 4);
            lsumr[i] = lsumr[i] * rs + ls;
            mrow[i] = mn;
            #pragma unroll
            for (int j = 0; j < 8; j++) acc[i][j] *= rs;
        }

        __syncwarp();

        #pragma unroll 4
        for (int k = 0; k < 64; k += 4) {
            float4 p0 = *(float4*)&Ps[(rq + 0) * 68 + k];
            float4 p1 = *(float4*)&Ps[(rq + 1) * 68 + k];
            float4 p2 = *(float4*)&Ps[(rq + 2) * 68 + k];
            float4 p3 = *(float4*)&Ps[(rq + 3) * 68 + k];
            #pragma unroll
            for (int kk2 = 0; kk2 < 4; kk2++) {
                float4 va = *(float4*)&Vs[(k + kk2) * 68 + kg * 4];
                float4 vb = *(float4*)&Vs[(k + kk2) * 68 + 32 + kg * 4];
                const float pv0 = (kk2 == 0) ? p0.x : (kk2 == 1) ? p0.y : (kk2 == 2) ? p0.z : p0.w;
                const float pv1 = (kk2 == 0) ? p1.x : (kk2 == 1) ? p1.y : (kk2 == 2) ? p1.z : p1.w;
                const float pv2 = (kk2 == 0) ? p2.x : (kk2 == 1) ? p2.y : (kk2 == 2) ? p2.z : p2.w;
                const float pv3 = (kk2 == 0) ? p3.x : (kk2 == 1) ? p3.y : (kk2 == 2) ? p3.z : p3.w;
                acc[0][0] += pv0 * va.x; acc[0][1] += pv0 * va.y; acc[0][2] += pv0 * va.z; acc[0][3] += pv0 * va.w;
                acc[0][4] += pv0 * vb.x; acc[0][5] += pv0 * vb.y; acc[0][6] += pv0 * vb.z; acc[0][7] += pv0 * vb.w;
                acc[1][0] += pv1 * va.x; acc[1][1] += pv1 * va.y; acc[1][2] += pv1 * va.z; acc[1][3] += pv1 * va.w;
                acc[1][4] += pv1 * vb.x; acc[1][5] += pv1 * vb.y; acc[1][6] += pv1 * vb.z; acc[1][7] += pv1 * vb.w;
                acc[2][0] += pv2 * va.x; acc[2][1] += pv2 * va.y; acc[2][2] += pv2 * va.z; acc[2][3] += pv2 * va.w;
                acc[2][4] += pv2 * vb.x; acc[2][5] += pv2 * vb.y; acc[2][6] += pv2 * vb.z; acc[2][7] += pv2 * vb.w;
                acc[3][0] += pv3 * va.x; acc[3][1] += pv3 * va.y; acc[3][2] += pv3 * va.z; acc[3][3] += pv3 * va.w;
                acc[3][4] += pv3 * vb.x; acc[3][5] += pv3 * vb.y; acc[3][6] += pv3 * vb.z; acc[3][7] += pv3 * vb.w;
            }
        }
    }

    const int eA = h * 64 + kg * 4;
    #pragma unroll
    for (int i = 0; i < 4; i++) {
        const float inv = 1.f / lsumr[i];
        const size_t idx = (size_t)(b * S_ + chunkStart + rq + i) * E_;
        store4split(acc[i][0] * inv, acc[i][1] * inv, acc[i][2] * inv, acc[i][3] * inv, idx + eA);
        store4split(acc[i][4] * inv, acc[i][5] * inv, acc[i][6] * inv, acc[i][7] * inv, idx + eA + 32);
    }
}

// ---------------------------------------------------------------------------
extern "C" void kernel_launch(void* const* d_in, const int* in_sizes, int n_in,
                              void* d_out, int out_size)
{
    const float* X  = (const float*)d_in[0];
    const float* Wq = (const float*)d_in[1];
    const float* bq = (const float*)d_in[2];
    const float* Wk = (const float*)d_in[3];
    const float* bk = (const float*)d_in[4];
    const float* Wv = (const float*)d_in[5];
    const float* bv = (const float*)d_in[6];
    const float* Wo = (const float*)d_in[7];
    const float* bo = (const float*)d_in[8];
    float* out = (float*)d_out;

    cudaFuncSetAttribute(attn_kernel, cudaFuncAttributeMaxDynamicSharedMemorySize, ATTN_SMEM_BYTES);
    cudaFuncSetAttribute(gemm_mma,    cudaFuncAttributeMaxDynamicSharedMemorySize, GEMM_SMEM);

    convert_x<<<(MTOT * E_) / (256 * 4), 256>>>(X);
    transpose_w<<<dim3(E_ / 32, E_ / 32, 4), dim3(32, 8)>>>(Wq, Wk, Wv, Wo);

    gemm_mma<<<dim3(18, MTOT / 128), 256, GEMM_SMEM>>>(1, bq, bk, bv, nullptr);

    attn_kernel<<<dim3(S_ / C_, H_, B_), 128, ATTN_SMEM_BYTES>>>();

    gemm_mma<<<dim3(6, MTOT / 128), 256, GEMM_SMEM>>>(0, bo, nullptr, nullptr, out);
}

// round 7
// speedup vs baseline: 3.8583x; 1.7733x over previous
#include <cuda_runtime.h>
#include <cuda_bf16.h>
#include <math.h>
#include <stdint.h>

#define B_ 2
#define S_ 4096
#define E_ 768
#define H_ 12
#define D_ 64
#define C_ 64
#define R_ 256
#define MTOT (B_*S_)

// bf16 split operands
__device__ __nv_bfloat16 g_xhi[MTOT*E_];
__device__ __nv_bfloat16 g_xlo[MTOT*E_];
__device__ __nv_bfloat16 g_wt_hi[4*E_*E_];   // [z*768+n][k]: Wq^T,Wk^T,Wv^T,Wo^T
__device__ __nv_bfloat16 g_wt_lo[4*E_*E_];
__device__ __nv_bfloat16 g_qhi[B_*H_*S_*D_];
__device__ __nv_bfloat16 g_qlo[B_*H_*S_*D_];
__device__ __nv_bfloat16 g_khi[B_*H_*S_*D_];
__device__ __nv_bfloat16 g_klo[B_*H_*S_*D_];
__device__ __nv_bfloat16 g_vhi[B_*H_*S_*D_];
__device__ __nv_bfloat16 g_vlo[B_*H_*S_*D_];
__device__ __nv_bfloat16 g_chi[MTOT*E_];
__device__ __nv_bfloat16 g_clo[MTOT*E_];

// ---------------------------------------------------------------------------
__device__ __forceinline__ uint32_t smem_u32(const void* p) {
    uint32_t a;
    asm("{ .reg .u64 t; cvta.to.shared.u64 t, %1; cvt.u32.u64 %0, t; }" : "=r"(a) : "l"(p));
    return a;
}
#define SWZ(off) ((off) ^ (((off) >> 3) & 0x70))

#define CP16(dst, src) \
    asm volatile("cp.async.cg.shared.global [%0], [%1], 16;" :: "r"(dst), "l"(src) : "memory")
#define CP_COMMIT() asm volatile("cp.async.commit_group;" ::: "memory")
#define CP_WAIT1()  asm volatile("cp.async.wait_group 1;" ::: "memory")
#define CP_WAIT0()  asm volatile("cp.async.wait_group 0;" ::: "memory")

#define LDMX4(r0, r1, r2, r3, a) \
    asm volatile("ldmatrix.sync.aligned.m8n8.x4.shared.b16 {%0,%1,%2,%3}, [%4];" \
                 : "=r"(r0), "=r"(r1), "=r"(r2), "=r"(r3) : "r"(a))
#define LDMX4T(r0, r1, r2, r3, a) \
    asm volatile("ldmatrix.sync.aligned.m8n8.x4.trans.shared.b16 {%0,%1,%2,%3}, [%4];" \
                 : "=r"(r0), "=r"(r1), "=r"(r2), "=r"(r3) : "r"(a))

#define MMA_BF16(d, a, b) \
    asm volatile("mma.sync.aligned.m16n8k16.row.col.f32.bf16.bf16.f32 " \
                 "{%0,%1,%2,%3}, {%4,%5,%6,%7}, {%8,%9}, {%0,%1,%2,%3};" \
                 : "+f"((d)[0]), "+f"((d)[1]), "+f"((d)[2]), "+f"((d)[3]) \
                 : "r"((a)[0]), "r"((a)[1]), "r"((a)[2]), "r"((a)[3]), \
                   "r"((b)[0]), "r"((b)[1]))

__device__ __forceinline__ uint32_t packbf2(float lo, float hi) {
    uint32_t r;
    asm("cvt.rn.bf16x2.f32 %0, %1, %2;" : "=r"(r) : "f"(hi), "f"(lo));
    return r;
}
__device__ __forceinline__ float bfres(float x) {
    return x - __bfloat162float(__float2bfloat16(x));
}

// ---------------------------------------------------------------------------
// prep kernels
// ---------------------------------------------------------------------------
__global__ __launch_bounds__(256)
void convert_x(const float* __restrict__ X)
{
    size_t i = ((size_t)blockIdx.x * 256 + threadIdx.x) * 4;
    float4 v = *(const float4*)(X + i);
    uint2 hi, lo;
    hi.x = packbf2(v.x, v.y); hi.y = packbf2(v.z, v.w);
    lo.x = packbf2(bfres(v.x), bfres(v.y));
    lo.y = packbf2(bfres(v.z), bfres(v.w));
    *(uint2*)&g_xhi[i] = hi;
    *(uint2*)&g_xlo[i] = lo;
}

__global__ __launch_bounds__(256)
void transpose_w(const float* __restrict__ Wq, const float* __restrict__ Wk,
                 const float* __restrict__ Wv, const float* __restrict__ Wo)
{
    __shared__ float st[32][33];
    const int z = blockIdx.z;
    const float* __restrict__ W = (z == 0) ? Wq : (z == 1) ? Wk : (z == 2) ? Wv : Wo;
    const int n0 = blockIdx.x * 32, k0 = blockIdx.y * 32;
    const int tx = threadIdx.x, ty = threadIdx.y;
    #pragma unroll
    for (int j = 0; j < 4; j++)
        st[ty + 8 * j][tx] = W[(size_t)(k0 + ty + 8 * j) * E_ + n0 + tx];
    __syncthreads();
    #pragma unroll
    for (int j = 0; j < 4; j++) {
        float v = st[tx][ty + 8 * j];
        size_t dst = (size_t)(z * E_ + n0 + ty + 8 * j) * E_ + k0 + tx;
        __nv_bfloat16 h = __float2bfloat16(v);
        g_wt_hi[dst] = h;
        g_wt_lo[dst] = __float2bfloat16(v - __bfloat162float(h));
    }
}

// ---------------------------------------------------------------------------
// mma.sync GEMM (as R6). qkvmode=1 writes q/k/v as bf16 hi/lo in (b,h,s,d).
// ---------------------------------------------------------------------------
#define BKC 64
#define NCH (E_/BKC)
#define BUFB 65536
#define GEMM_SMEM (2*BUFB)

__global__ __launch_bounds__(256)
void gemm_mma(int qkvmode,
              const float* __restrict__ bias0, const float* __restrict__ bias1,
              const float* __restrict__ bias2, float* __restrict__ outp)
{
    extern __shared__ char smem[];
    const uint32_t sb = smem_u32(smem);
    const int tid = threadIdx.x;
    const int wid = tid >> 5, lane = tid & 31;
    const int wm = wid >> 2, wn = wid & 3;
    const int m0 = blockIdx.y * 128, n0 = blockIdx.x * 128;

    const __nv_bfloat16* __restrict__ Ah = qkvmode ? g_xhi : g_chi;
    const __nv_bfloat16* __restrict__ Al = qkvmode ? g_xlo : g_clo;
    const __nv_bfloat16* __restrict__ Bh = g_wt_hi + (qkvmode ? 0 : (size_t)2304 * E_);
    const __nv_bfloat16* __restrict__ Bl = g_wt_lo + (qkvmode ? 0 : (size_t)2304 * E_);

    float acc[4][4][4];
    #pragma unroll
    for (int i = 0; i < 4; i++)
        #pragma unroll
        for (int j = 0; j < 4; j++)
            #pragma unroll
            for (int q = 0; q < 4; q++) acc[i][j][q] = 0.f;

    auto issue = [&](int c, int b) {
        const uint32_t bo = sb + b * BUFB;
        #pragma unroll
        for (int it = 0; it < 4; it++) {
            const int u = tid + 256 * it;
            const int row = u >> 3, cu = u & 7;
            const size_t ga = (size_t)(m0 + row) * E_ + c * BKC + cu * 8;
            const size_t gb = (size_t)(n0 + row) * E_ + c * BKC + cu * 8;
            const uint32_t so = SWZ((uint32_t)(row * 128 + cu * 16));
            CP16(bo + 0     + so, Ah + ga);
            CP16(bo + 16384 + so, Al + ga);
            CP16(bo + 32768 + so, Bh + gb);
            CP16(bo + 49152 + so, Bl + gb);
        }
        CP_COMMIT();
    };

    issue(0, 0);

    const int arow = (lane & 15);
    const int au   = (lane >> 4);
    const int brow = ((lane >> 4) << 3) + (lane & 7);
    const int bu   = ((lane >> 3) & 1);

    for (int c = 0; c < NCH; c++) {
        if (c + 1 < NCH) { issue(c + 1, (c + 1) & 1); CP_WAIT1(); }
        else             { CP_WAIT0(); }
        __syncthreads();

        const uint32_t bo = sb + (c & 1) * BUFB;
        const uint32_t sAh = bo, sAl = bo + 16384, sBh = bo + 32768, sBl = bo + 49152;

        #pragma unroll
        for (int ks = 0; ks < 4; ks++) {
            uint32_t ah[4][4], al[4][4], bh[4][2], bl[4][2];
            #pragma unroll
            for (int mt = 0; mt < 4; mt++) {
                const int r = wm * 64 + mt * 16 + arow;
                const int u = ks * 2 + au;
                const uint32_t off = r * 128 + ((u ^ (r & 7)) << 4);
                LDMX4(ah[mt][0], ah[mt][1], ah[mt][2], ah[mt][3], sAh + off);
                LDMX4(al[mt][0], al[mt][1], al[mt][2], al[mt][3], sAl + off);
            }
            #pragma unroll
            for (int half = 0; half < 2; half++) {
                const int r = wn * 32 + half * 16 + brow;
                const int u = ks * 2 + bu;
                const uint32_t off = r * 128 + ((u ^ (r & 7)) << 4);
                LDMX4(bh[half*2][0], bh[half*2][1], bh[half*2+1][0], bh[half*2+1][1], sBh + off);
                LDMX4(bl[half*2][0], bl[half*2][1], bl[half*2+1][0], bl[half*2+1][1], sBl + off);
            }
            #pragma unroll
            for (int mi = 0; mi < 4; mi++)
                #pragma unroll
                for (int ni = 0; ni < 4; ni++) {
                    MMA_BF16(acc[mi][ni], ah[mi], bh[ni]);
                    MMA_BF16(acc[mi][ni], ah[mi], bl[ni]);
                    MMA_BF16(acc[mi][ni], al[mi], bh[ni]);
                }
        }
        __syncthreads();
    }

    const int g = lane >> 2, tig = lane & 3;
    #pragma unroll
    for (int ni = 0; ni < 4; ni++) {
        const int col = n0 + wn * 32 + ni * 8 + 2 * tig;
        if (qkvmode) {
            const int z = (col >= 1536) ? 2 : (col >= 768) ? 1 : 0;
            const int n_in = col - z * 768;
            const float* bias = (z == 0) ? bias0 : (z == 1) ? bias1 : bias2;
            const float2 bi = *(const float2*)&bias[n_in];
            const float scale = (z == 0) ? 0.125f : 1.0f;
            __nv_bfloat16* dHi = (z == 0) ? g_qhi : (z == 1) ? g_khi : g_vhi;
            __nv_bfloat16* dLo = (z == 0) ? g_qlo : (z == 1) ? g_klo : g_vlo;
            const int h = n_in >> 6, d = n_in & 63;
            #pragma unroll
            for (int mi = 0; mi < 4; mi++) {
                #pragma unroll
                for (int hf = 0; hf < 2; hf++) {
                    const int row = m0 + wm * 64 + mi * 16 + g + hf * 8;
                    const int bb = row >> 12, s = row & (S_ - 1);
                    const float v0 = (acc[mi][ni][hf*2+0] + bi.x) * scale;
                    const float v1 = (acc[mi][ni][hf*2+1] + bi.y) * scale;
                    const size_t idx = ((size_t)(bb * H_ + h) * S_ + s) * D_ + d;
                    *(uint32_t*)&dHi[idx] = packbf2(v0, v1);
                    *(uint32_t*)&dLo[idx] = packbf2(bfres(v0), bfres(v1));
                }
            }
        } else {
            const float2 bi = *(const float2*)&bias0[col];
            #pragma unroll
            for (int mi = 0; mi < 4; mi++) {
                #pragma unroll
                for (int hf = 0; hf < 2; hf++) {
                    const int row = m0 + wm * 64 + mi * 16 + g + hf * 8;
                    float2 o;
                    o.x = acc[mi][ni][hf*2+0] + bi.x;
                    o.y = acc[mi][ni][hf*2+1] + bi.y;
                    *(float2*)&outp[(size_t)row * E_ + col] = o;
                }
            }
        }
    }
}

// ---------------------------------------------------------------------------
// Flash attention on mma.sync. 128 threads = 4 warps x 16 q-rows.
// Smem: Qhi|Qlo (16KB) + 2 x (Khi|Klo|Vhi|Vlo) (2 x 32KB) = 80KB.
// ---------------------------------------------------------------------------
#define AT_SMEM 81920

__global__ __launch_bounds__(128)
void attn_kernel()
{
    extern __shared__ char smraw[];
    const uint32_t sb = smem_u32(smraw);
    const int tid = threadIdx.x;
    const int wid = tid >> 5, lane = tid & 31;
    const int g = lane >> 2, tig = lane & 3;
    const int chunk = blockIdx.x, h = blockIdx.y, b = blockIdx.z;
    const int cs = chunk * C_;
    const size_t base = (size_t)(b * H_ + h) * S_ * D_;

    const uint32_t sQh = sb, sQl = sb + 8192;
    const uint32_t sKV = sb + 16384;   // + buf*32768 + {0,8192,16384,24576}

    // load Q (hi/lo)
    {
        #pragma unroll
        for (int it = 0; it < 4; it++) {
            const int u = tid + 128 * it;
            const int row = u >> 3, cu = u & 7;
            const size_t gq = base + (size_t)(cs + row) * D_ + cu * 8;
            const uint32_t so = SWZ((uint32_t)(row * 128 + cu * 16));
            CP16(sQh + so, g_qhi + gq);
            CP16(sQl + so, g_qlo + gq);
        }
        CP_COMMIT();
    }

    const int t0 = (cs < R_) ? (R_ - cs) / C_ : 0;
    const int t1e = (S_ - cs + R_) / C_;
    const int t1 = (t1e < 9) ? t1e : 9;
    const int ntiles = t1 - t0;

    auto issueKV = [&](int t, int buf) {
        const int tstart = cs - R_ + t * C_;
        const uint32_t bo = sKV + buf * 32768;
        #pragma unroll
        for (int it = 0; it < 4; it++) {
            const int u = tid + 128 * it;
            const int row = u >> 3, cu = u & 7;
            const size_t gk = base + (size_t)(tstart + row) * D_ + cu * 8;
            const uint32_t so = SWZ((uint32_t)(row * 128 + cu * 16));
            CP16(bo + 0     + so, g_khi + gk);
            CP16(bo + 8192  + so, g_klo + gk);
            CP16(bo + 16384 + so, g_vhi + gk);
            CP16(bo + 24576 + so, g_vlo + gk);
        }
        CP_COMMIT();
    };

    issueKV(t0, 0);

    float oacc[8][4];
    #pragma unroll
    for (int i = 0; i < 8; i++)
        #pragma unroll
        for (int j = 0; j < 4; j++) oacc[i][j] = 0.f;
    float m0 = -INFINITY, m1 = -INFINITY, l0 = 0.f, l1 = 0.f;

    // ldmatrix lane params
    const int qrow = wid * 16 + (lane & 15);
    const int qau  = (lane >> 4);
    const int kbrow = ((lane >> 4) << 3) + (lane & 7);
    const int kbu   = ((lane >> 3) & 1);
    const int vrow_l = (lane & 7) + 8 * ((lane >> 3) & 1);
    const int vnu    = (lane >> 4);

    for (int tt = 0; tt < ntiles; tt++) {
        if (tt + 1 < ntiles) { issueKV(t0 + tt + 1, (tt + 1) & 1); CP_WAIT1(); }
        else                 { CP_WAIT0(); }
        __syncthreads();

        const uint32_t bo = sKV + (tt & 1) * 32768;
        const uint32_t sKh = bo, sKl = bo + 8192, sVh = bo + 16384, sVl = bo + 24576;

        // ---- QK: scores 16x64 per warp ----
        float sc[8][4];
        #pragma unroll
        for (int i = 0; i < 8; i++)
            #pragma unroll
            for (int j = 0; j < 4; j++) sc[i][j] = 0.f;

        #pragma unroll
        for (int ks = 0; ks < 4; ks++) {
            uint32_t ah[4], al[4];
            {
                const int u = ks * 2 + qau;
                const uint32_t off = qrow * 128 + ((u ^ (qrow & 7)) << 4);
                LDMX4(ah[0], ah[1], ah[2], ah[3], sQh + off);
                LDMX4(al[0], al[1], al[2], al[3], sQl + off);
            }
            #pragma unroll
            for (int hf = 0; hf < 4; hf++) {
                const int r = hf * 16 + kbrow;
                const int u = ks * 2 + kbu;
                const uint32_t off = r * 128 + ((u ^ (r & 7)) << 4);
                uint32_t bh[2][2], bl[2][2];
                LDMX4(bh[0][0], bh[0][1], bh[1][0], bh[1][1], sKh + off);
                LDMX4(bl[0][0], bl[0][1], bl[1][0], bl[1][1], sKl + off);
                #pragma unroll
                for (int t = 0; t < 2; t++) {
                    MMA_BF16(sc[2*hf+t], ah, bh[t]);
                    MMA_BF16(sc[2*hf+t], ah, bl[t]);
                    MMA_BF16(sc[2*hf+t], al, bh[t]);
                }
            }
        }

        // ---- online softmax (rows g and g+8) ----
        {
            float mx0 = sc[0][0], mx1 = sc[0][2];
            #pragma unroll
            for (int i = 0; i < 8; i++) {
                mx0 = fmaxf(mx0, fmaxf(sc[i][0], sc[i][1]));
                mx1 = fmaxf(mx1, fmaxf(sc[i][2], sc[i][3]));
            }
            mx0 = fmaxf(mx0, __shfl_xor_sync(0xffffffffu, mx0, 1));
            mx0 = fmaxf(mx0, __shfl_xor_sync(0xffffffffu, mx0, 2));
            mx1 = fmaxf(mx1, __shfl_xor_sync(0xffffffffu, mx1, 1));
            mx1 = fmaxf(mx1, __shfl_xor_sync(0xffffffffu, mx1, 2));
            const float mn0 = fmaxf(m0, mx0), mn1 = fmaxf(m1, mx1);
            const float rs0 = __expf(m0 - mn0), rs1 = __expf(m1 - mn1);
            m0 = mn0; m1 = mn1;
            float ls0 = 0.f, ls1 = 0.f;
            #pragma unroll
            for (int i = 0; i < 8; i++) {
                sc[i][0] = __expf(sc[i][0] - mn0);
                sc[i][1] = __expf(sc[i][1] - mn0);
                sc[i][2] = __expf(sc[i][2] - mn1);
                sc[i][3] = __expf(sc[i][3] - mn1);
                ls0 += sc[i][0] + sc[i][1];
                ls1 += sc[i][2] + sc[i][3];
            }
            ls0 += __shfl_xor_sync(0xffffffffu, ls0, 1);
            ls0 += __shfl_xor_sync(0xffffffffu, ls0, 2);
            ls1 += __shfl_xor_sync(0xffffffffu, ls1, 1);
            ls1 += __shfl_xor_sync(0xffffffffu, ls1, 2);
            l0 = l0 * rs0 + ls0;
            l1 = l1 * rs1 + ls1;
            #pragma unroll
            for (int i = 0; i < 8; i++) {
                oacc[i][0] *= rs0; oacc[i][1] *= rs0;
                oacc[i][2] *= rs1; oacc[i][3] *= rs1;
            }
        }

        // ---- PV: out 16x64 per warp ----
        #pragma unroll
        for (int ks = 0; ks < 4; ks++) {
            uint32_t ap[4], apl[4];
            {
                const float p00 = sc[2*ks][0],   p01 = sc[2*ks][1];
                const float p10 = sc[2*ks][2],   p11 = sc[2*ks][3];
                const float p20 = sc[2*ks+1][0], p21 = sc[2*ks+1][1];
                const float p30 = sc[2*ks+1][2], p31 = sc[2*ks+1][3];
                ap[0]  = packbf2(p00, p01);
                ap[1]  = packbf2(p10, p11);
                ap[2]  = packbf2(p20, p21);
                ap[3]  = packbf2(p30, p31);
                apl[0] = packbf2(bfres(p00), bfres(p01));
                apl[1] = packbf2(bfres(p10), bfres(p11));
                apl[2] = packbf2(bfres(p20), bfres(p21));
                apl[3] = packbf2(bfres(p30), bfres(p31));
            }
            #pragma unroll
            for (int hf = 0; hf < 4; hf++) {
                const int r = ks * 16 + vrow_l;
                const int u = hf * 2 + vnu;
                const uint32_t off = r * 128 + ((u ^ (r & 7)) << 4);
                uint32_t vh[2][2], vl[2][2];
                LDMX4T(vh[0][0], vh[0][1], vh[1][0], vh[1][1], sVh + off);
                LDMX4T(vl[0][0], vl[0][1], vl[1][0], vl[1][1], sVl + off);
                #pragma unroll
                for (int t = 0; t < 2; t++) {
                    MMA_BF16(oacc[2*hf+t], ap, vh[t]);
                    MMA_BF16(oacc[2*hf+t], ap, vl[t]);
                    MMA_BF16(oacc[2*hf+t], apl, vh[t]);
                }
            }
        }
        __syncthreads();
    }

    // ---- epilogue: ctx = oacc / l -> bf16 hi/lo, layout (b, s, h*64+d) ----
    const float inv0 = 1.f / l0, inv1 = 1.f / l1;
    const int row0 = cs + wid * 16 + g;
    #pragma unroll
    for (int ni = 0; ni < 8; ni++) {
        const int d = ni * 8 + 2 * tig;
        const size_t i0 = (size_t)(b * S_ + row0) * E_ + h * 64 + d;
        const size_t i1 = (size_t)(b * S_ + row0 + 8) * E_ + h * 64 + d;
        const float v00 = oacc[ni][0] * inv0, v01 = oacc[ni][1] * inv0;
        const float v10 = oacc[ni][2] * inv1, v11 = oacc[ni][3] * inv1;
        *(uint32_t*)&g_chi[i0] = packbf2(v00, v01);
        *(uint32_t*)&g_clo[i0] = packbf2(bfres(v00), bfres(v01));
        *(uint32_t*)&g_chi[i1] = packbf2(v10, v11);
        *(uint32_t*)&g_clo[i1] = packbf2(bfres(v10), bfres(v11));
    }
}

// ---------------------------------------------------------------------------
extern "C" void kernel_launch(void* const* d_in, const int* in_sizes, int n_in,
                              void* d_out, int out_size)
{
    const float* X  = (const float*)d_in[0];
    const float* Wq = (const float*)d_in[1];
    const float* bq = (const float*)d_in[2];
    const float* Wk = (const float*)d_in[3];
    const float* bk = (const float*)d_in[4];
    const float* Wv = (const float*)d_in[5];
    const float* bv = (const float*)d_in[6];
    const float* Wo = (const float*)d_in[7];
    const float* bo = (const float*)d_in[8];
    float* out = (float*)d_out;

    cudaFuncSetAttribute(attn_kernel, cudaFuncAttributeMaxDynamicSharedMemorySize, AT_SMEM);
    cudaFuncSetAttribute(gemm_mma,    cudaFuncAttributeMaxDynamicSharedMemorySize, GEMM_SMEM);

    convert_x<<<(MTOT * E_) / (256 * 4), 256>>>(X);
    transpose_w<<<dim3(E_ / 32, E_ / 32, 4), dim3(32, 8)>>>(Wq, Wk, Wv, Wo);

    gemm_mma<<<dim3(18, MTOT / 128), 256, GEMM_SMEM>>>(1, bq, bk, bv, nullptr);

    attn_kernel<<<dim3(S_ / C_, H_, B_), 128, AT_SMEM>>>();

    gemm_mma<<<dim3(6, MTOT / 128), 256, GEMM_SMEM>>>(0, bo, nullptr, nullptr, out);
}

// round 8
// speedup vs baseline: 3.9566x; 1.0255x over previous
#include <cuda_runtime.h>
#include <cuda_bf16.h>
#include <math.h>
#include <stdint.h>

#define B_ 2
#define S_ 4096
#define E_ 768
#define H_ 12
#define D_ 64
#define C_ 64
#define R_ 256
#define MTOT (B_*S_)

// bf16 split operands
__device__ __nv_bfloat16 g_xhi[MTOT*E_];
__device__ __nv_bfloat16 g_xlo[MTOT*E_];
__device__ __nv_bfloat16 g_wt_hi[4*E_*E_];   // [z*768+n][k]: Wq^T,Wk^T,Wv^T,Wo^T
__device__ __nv_bfloat16 g_wt_lo[4*E_*E_];
__device__ __nv_bfloat16 g_qhi[B_*H_*S_*D_];
__device__ __nv_bfloat16 g_qlo[B_*H_*S_*D_];
__device__ __nv_bfloat16 g_khi[B_*H_*S_*D_];
__device__ __nv_bfloat16 g_klo[B_*H_*S_*D_];
__device__ __nv_bfloat16 g_vhi[B_*H_*S_*D_];
__device__ __nv_bfloat16 g_vlo[B_*H_*S_*D_];
__device__ __nv_bfloat16 g_chi[MTOT*E_];
__device__ __nv_bfloat16 g_clo[MTOT*E_];

// ---------------------------------------------------------------------------
__device__ __forceinline__ uint32_t smem_u32(const void* p) {
    uint32_t a;
    asm("{ .reg .u64 t; cvta.to.shared.u64 t, %1; cvt.u32.u64 %0, t; }" : "=r"(a) : "l"(p));
    return a;
}
#define SWZ(off) ((off) ^ (((off) >> 3) & 0x70))

#define CP16(dst, src) \
    asm volatile("cp.async.cg.shared.global [%0], [%1], 16;" :: "r"(dst), "l"(src) : "memory")
#define CP_COMMIT() asm volatile("cp.async.commit_group;" ::: "memory")
#define CP_WAIT1()  asm volatile("cp.async.wait_group 1;" ::: "memory")
#define CP_WAIT0()  asm volatile("cp.async.wait_group 0;" ::: "memory")

#define LDMX4(r0, r1, r2, r3, a) \
    asm volatile("ldmatrix.sync.aligned.m8n8.x4.shared.b16 {%0,%1,%2,%3}, [%4];" \
                 : "=r"(r0), "=r"(r1), "=r"(r2), "=r"(r3) : "r"(a))
#define LDMX4T(r0, r1, r2, r3, a) \
    asm volatile("ldmatrix.sync.aligned.m8n8.x4.trans.shared.b16 {%0,%1,%2,%3}, [%4];" \
                 : "=r"(r0), "=r"(r1), "=r"(r2), "=r"(r3) : "r"(a))

#define MMA_BF16(d, a, b) \
    asm volatile("mma.sync.aligned.m16n8k16.row.col.f32.bf16.bf16.f32 " \
                 "{%0,%1,%2,%3}, {%4,%5,%6,%7}, {%8,%9}, {%0,%1,%2,%3};" \
                 : "+f"((d)[0]), "+f"((d)[1]), "+f"((d)[2]), "+f"((d)[3]) \
                 : "r"((a)[0]), "r"((a)[1]), "r"((a)[2]), "r"((a)[3]), \
                   "r"((b)[0]), "r"((b)[1]))

__device__ __forceinline__ uint32_t packbf2(float lo, float hi) {
    uint32_t r;
    asm("cvt.rn.bf16x2.f32 %0, %1, %2;" : "=r"(r) : "f"(hi), "f"(lo));
    return r;
}
__device__ __forceinline__ float bfres(float x) {
    return x - __bfloat162float(__float2bfloat16(x));
}

// ---------------------------------------------------------------------------
// prep kernels
// ---------------------------------------------------------------------------
__global__ __launch_bounds__(256)
void convert_x(const float* __restrict__ X)
{
    size_t i = ((size_t)blockIdx.x * 256 + threadIdx.x) * 4;
    float4 v = *(const float4*)(X + i);
    uint2 hi, lo;
    hi.x = packbf2(v.x, v.y); hi.y = packbf2(v.z, v.w);
    lo.x = packbf2(bfres(v.x), bfres(v.y));
    lo.y = packbf2(bfres(v.z), bfres(v.w));
    *(uint2*)&g_xhi[i] = hi;
    *(uint2*)&g_xlo[i] = lo;
}

__global__ __launch_bounds__(256)
void transpose_w(const float* __restrict__ Wq, const float* __restrict__ Wk,
                 const float* __restrict__ Wv, const float* __restrict__ Wo)
{
    __shared__ float st[32][33];
    const int z = blockIdx.z;
    const float* __restrict__ W = (z == 0) ? Wq : (z == 1) ? Wk : (z == 2) ? Wv : Wo;
    const int n0 = blockIdx.x * 32, k0 = blockIdx.y * 32;
    const int tx = threadIdx.x, ty = threadIdx.y;
    #pragma unroll
    for (int j = 0; j < 4; j++)
        st[ty + 8 * j][tx] = W[(size_t)(k0 + ty + 8 * j) * E_ + n0 + tx];
    __syncthreads();
    #pragma unroll
    for (int j = 0; j < 4; j++) {
        float v = st[tx][ty + 8 * j];
        size_t dst = (size_t)(z * E_ + n0 + ty + 8 * j) * E_ + k0 + tx;
        __nv_bfloat16 h = __float2bfloat16(v);
        g_wt_hi[dst] = h;
        g_wt_lo[dst] = __float2bfloat16(v - __bfloat162float(h));
    }
}

// ---------------------------------------------------------------------------
// mma.sync GEMM, 3-stage cp.async pipeline, one sync per chunk.
// ---------------------------------------------------------------------------
#define BKC 64
#define NCH (E_/BKC)
#define BUFB 65536
#define GEMM_SMEM (3*BUFB)      // 196608

__global__ __launch_bounds__(256)
void gemm_mma(int qkvmode,
              const float* __restrict__ bias0, const float* __restrict__ bias1,
              const float* __restrict__ bias2, float* __restrict__ outp)
{
    extern __shared__ char smem[];
    const uint32_t sb = smem_u32(smem);
    const int tid = threadIdx.x;
    const int wid = tid >> 5, lane = tid & 31;
    const int wm = wid >> 2, wn = wid & 3;
    const int m0 = blockIdx.y * 128, n0 = blockIdx.x * 128;

    const __nv_bfloat16* __restrict__ Ah = qkvmode ? g_xhi : g_chi;
    const __nv_bfloat16* __restrict__ Al = qkvmode ? g_xlo : g_clo;
    const __nv_bfloat16* __restrict__ Bh = g_wt_hi + (qkvmode ? 0 : (size_t)2304 * E_);
    const __nv_bfloat16* __restrict__ Bl = g_wt_lo + (qkvmode ? 0 : (size_t)2304 * E_);

    float acc[4][4][4];
    #pragma unroll
    for (int i = 0; i < 4; i++)
        #pragma unroll
        for (int j = 0; j < 4; j++)
            #pragma unroll
            for (int q = 0; q < 4; q++) acc[i][j][q] = 0.f;

    auto issue = [&](int c) {
        const uint32_t bo = sb + (c % 3) * BUFB;
        #pragma unroll
        for (int it = 0; it < 4; it++) {
            const int u = tid + 256 * it;
            const int row = u >> 3, cu = u & 7;
            const size_t ga = (size_t)(m0 + row) * E_ + c * BKC + cu * 8;
            const size_t gb = (size_t)(n0 + row) * E_ + c * BKC + cu * 8;
            const uint32_t so = SWZ((uint32_t)(row * 128 + cu * 16));
            CP16(bo + 0     + so, Ah + ga);
            CP16(bo + 16384 + so, Al + ga);
            CP16(bo + 32768 + so, Bh + gb);
            CP16(bo + 49152 + so, Bl + gb);
        }
        CP_COMMIT();
    };

    issue(0);
    issue(1);

    const int arow = (lane & 15);
    const int au   = (lane >> 4);
    const int brow = ((lane >> 4) << 3) + (lane & 7);
    const int bu   = ((lane >> 3) & 1);

    for (int c = 0; c < NCH; c++) {
        if (c + 1 < NCH) CP_WAIT1(); else CP_WAIT0();
        __syncthreads();
        if (c + 2 < NCH) issue(c + 2);   // safe: all warps finished buffer (c+2)%3

        const uint32_t bo = sb + (c % 3) * BUFB;
        const uint32_t sAh = bo, sAl = bo + 16384, sBh = bo + 32768, sBl = bo + 49152;

        #pragma unroll
        for (int ks = 0; ks < 4; ks++) {
            uint32_t ah[4][4], al[4][4], bh[4][2], bl[4][2];
            #pragma unroll
            for (int mt = 0; mt < 4; mt++) {
                const int r = wm * 64 + mt * 16 + arow;
                const int u = ks * 2 + au;
                const uint32_t off = r * 128 + ((u ^ (r & 7)) << 4);
                LDMX4(ah[mt][0], ah[mt][1], ah[mt][2], ah[mt][3], sAh + off);
                LDMX4(al[mt][0], al[mt][1], al[mt][2], al[mt][3], sAl + off);
            }
            #pragma unroll
            for (int half = 0; half < 2; half++) {
                const int r = wn * 32 + half * 16 + brow;
                const int u = ks * 2 + bu;
                const uint32_t off = r * 128 + ((u ^ (r & 7)) << 4);
                LDMX4(bh[half*2][0], bh[half*2][1], bh[half*2+1][0], bh[half*2+1][1], sBh + off);
                LDMX4(bl[half*2][0], bl[half*2][1], bl[half*2+1][0], bl[half*2+1][1], sBl + off);
            }
            #pragma unroll
            for (int mi = 0; mi < 4; mi++)
                #pragma unroll
                for (int ni = 0; ni < 4; ni++) {
                    MMA_BF16(acc[mi][ni], ah[mi], bh[ni]);
                    MMA_BF16(acc[mi][ni], ah[mi], bl[ni]);
                    MMA_BF16(acc[mi][ni], al[mi], bh[ni]);
                }
        }
    }

    const int g = lane >> 2, tig = lane & 3;
    #pragma unroll
    for (int ni = 0; ni < 4; ni++) {
        const int col = n0 + wn * 32 + ni * 8 + 2 * tig;
        if (qkvmode) {
            const int z = (col >= 1536) ? 2 : (col >= 768) ? 1 : 0;
            const int n_in = col - z * 768;
            const float* bias = (z == 0) ? bias0 : (z == 1) ? bias1 : bias2;
            const float2 bi = *(const float2*)&bias[n_in];
            const float scale = (z == 0) ? 0.125f : 1.0f;
            __nv_bfloat16* dHi = (z == 0) ? g_qhi : (z == 1) ? g_khi : g_vhi;
            __nv_bfloat16* dLo = (z == 0) ? g_qlo : (z == 1) ? g_klo : g_vlo;
            const int h = n_in >> 6, d = n_in & 63;
            #pragma unroll
            for (int mi = 0; mi < 4; mi++) {
                #pragma unroll
                for (int hf = 0; hf < 2; hf++) {
                    const int row = m0 + wm * 64 + mi * 16 + g + hf * 8;
                    const int bb = row >> 12, s = row & (S_ - 1);
                    const float v0 = (acc[mi][ni][hf*2+0] + bi.x) * scale;
                    const float v1 = (acc[mi][ni][hf*2+1] + bi.y) * scale;
                    const size_t idx = ((size_t)(bb * H_ + h) * S_ + s) * D_ + d;
                    *(uint32_t*)&dHi[idx] = packbf2(v0, v1);
                    *(uint32_t*)&dLo[idx] = packbf2(bfres(v0), bfres(v1));
                }
            }
        } else {
            const float2 bi = *(const float2*)&bias0[col];
            #pragma unroll
            for (int mi = 0; mi < 4; mi++) {
                #pragma unroll
                for (int hf = 0; hf < 2; hf++) {
                    const int row = m0 + wm * 64 + mi * 16 + g + hf * 8;
                    float2 o;
                    o.x = acc[mi][ni][hf*2+0] + bi.x;
                    o.y = acc[mi][ni][hf*2+1] + bi.y;
                    *(float2*)&outp[(size_t)row * E_ + col] = o;
                }
            }
        }
    }
}

// ---------------------------------------------------------------------------
// Flash attention on mma.sync. 4 warps x 16 q-rows. Q fragments live in
// registers (staged once through smem); smem = 2 x 32KB KV buffers = 64KB.
// ---------------------------------------------------------------------------
#define AT_SMEM 65536

__global__ __launch_bounds__(128, 3)
void attn_kernel()
{
    extern __shared__ char smraw[];
    const uint32_t sb = smem_u32(smraw);
    const int tid = threadIdx.x;
    const int wid = tid >> 5, lane = tid & 31;
    const int g = lane >> 2, tig = lane & 3;
    const int chunk = blockIdx.x, h = blockIdx.y, b = blockIdx.z;
    const int cs = chunk * C_;
    const size_t base = (size_t)(b * H_ + h) * S_ * D_;

    // ---- stage Q through buf0, hoist fragments to registers ----
    uint32_t qh[4][4], ql[4][4];
    {
        const uint32_t sQh = sb, sQl = sb + 8192;
        #pragma unroll
        for (int it = 0; it < 4; it++) {
            const int u = tid + 128 * it;
            const int row = u >> 3, cu = u & 7;
            const size_t gq = base + (size_t)(cs + row) * D_ + cu * 8;
            const uint32_t so = SWZ((uint32_t)(row * 128 + cu * 16));
            CP16(sQh + so, g_qhi + gq);
            CP16(sQl + so, g_qlo + gq);
        }
        CP_COMMIT();
        CP_WAIT0();
        __syncthreads();
        const int qrow = wid * 16 + (lane & 15);
        const int qau  = (lane >> 4);
        #pragma unroll
        for (int ks = 0; ks < 4; ks++) {
            const int u = ks * 2 + qau;
            const uint32_t off = qrow * 128 + ((u ^ (qrow & 7)) << 4);
            LDMX4(qh[ks][0], qh[ks][1], qh[ks][2], qh[ks][3], sQh + off);
            LDMX4(ql[ks][0], ql[ks][1], ql[ks][2], ql[ks][3], sQl + off);
        }
        __syncthreads();   // all warps done with staged Q before KV overwrites
    }

    const int t0 = (cs < R_) ? (R_ - cs) / C_ : 0;
    const int t1e = (S_ - cs + R_) / C_;
    const int t1 = (t1e < 9) ? t1e : 9;
    const int ntiles = t1 - t0;

    auto issueKV = [&](int t, int buf) {
        const int tstart = cs - R_ + t * C_;
        const uint32_t bo = sb + buf * 32768;
        #pragma unroll
        for (int it = 0; it < 4; it++) {
            const int u = tid + 128 * it;
            const int row = u >> 3, cu = u & 7;
            const size_t gk = base + (size_t)(tstart + row) * D_ + cu * 8;
            const uint32_t so = SWZ((uint32_t)(row * 128 + cu * 16));
            CP16(bo + 0     + so, g_khi + gk);
            CP16(bo + 8192  + so, g_klo + gk);
            CP16(bo + 16384 + so, g_vhi + gk);
            CP16(bo + 24576 + so, g_vlo + gk);
        }
        CP_COMMIT();
    };

    issueKV(t0, 0);

    float oacc[8][4];
    #pragma unroll
    for (int i = 0; i < 8; i++)
        #pragma unroll
        for (int j = 0; j < 4; j++) oacc[i][j] = 0.f;
    float m0 = -INFINITY, m1 = -INFINITY, l0 = 0.f, l1 = 0.f;

    const int kbrow = ((lane >> 4) << 3) + (lane & 7);
    const int kbu   = ((lane >> 3) & 1);
    const int vrow_l = (lane & 7) + 8 * ((lane >> 3) & 1);
    const int vnu    = (lane >> 4);

    for (int tt = 0; tt < ntiles; tt++) {
        if (tt + 1 < ntiles) { issueKV(t0 + tt + 1, (tt + 1) & 1); CP_WAIT1(); }
        else                 { CP_WAIT0(); }
        __syncthreads();

        const uint32_t bo = sb + (tt & 1) * 32768;
        const uint32_t sKh = bo, sKl = bo + 8192, sVh = bo + 16384, sVl = bo + 24576;

        // ---- QK ----
        float sc[8][4];
        #pragma unroll
        for (int i = 0; i < 8; i++)
            #pragma unroll
            for (int j = 0; j < 4; j++) sc[i][j] = 0.f;

        #pragma unroll
        for (int ks = 0; ks < 4; ks++) {
            #pragma unroll
            for (int hf = 0; hf < 4; hf++) {
                const int r = hf * 16 + kbrow;
                const int u = ks * 2 + kbu;
                const uint32_t off = r * 128 + ((u ^ (r & 7)) << 4);
                uint32_t bh[2][2], bl[2][2];
                LDMX4(bh[0][0], bh[0][1], bh[1][0], bh[1][1], sKh + off);
                LDMX4(bl[0][0], bl[0][1], bl[1][0], bl[1][1], sKl + off);
                #pragma unroll
                for (int t = 0; t < 2; t++) {
                    MMA_BF16(sc[2*hf+t], qh[ks], bh[t]);
                    MMA_BF16(sc[2*hf+t], qh[ks], bl[t]);
                    MMA_BF16(sc[2*hf+t], ql[ks], bh[t]);
                }
            }
        }

        // ---- online softmax ----
        {
            float mx0 = sc[0][0], mx1 = sc[0][2];
            #pragma unroll
            for (int i = 0; i < 8; i++) {
                mx0 = fmaxf(mx0, fmaxf(sc[i][0], sc[i][1]));
                mx1 = fmaxf(mx1, fmaxf(sc[i][2], sc[i][3]));
            }
            mx0 = fmaxf(mx0, __shfl_xor_sync(0xffffffffu, mx0, 1));
            mx0 = fmaxf(mx0, __shfl_xor_sync(0xffffffffu, mx0, 2));
            mx1 = fmaxf(mx1, __shfl_xor_sync(0xffffffffu, mx1, 1));
            mx1 = fmaxf(mx1, __shfl_xor_sync(0xffffffffu, mx1, 2));
            const float mn0 = fmaxf(m0, mx0), mn1 = fmaxf(m1, mx1);
            const float rs0 = __expf(m0 - mn0), rs1 = __expf(m1 - mn1);
            m0 = mn0; m1 = mn1;
            float ls0 = 0.f, ls1 = 0.f;
            #pragma unroll
            for (int i = 0; i < 8; i++) {
                sc[i][0] = __expf(sc[i][0] - mn0);
                sc[i][1] = __expf(sc[i][1] - mn0);
                sc[i][2] = __expf(sc[i][2] - mn1);
                sc[i][3] = __expf(sc[i][3] - mn1);
                ls0 += sc[i][0] + sc[i][1];
                ls1 += sc[i][2] + sc[i][3];
            }
            ls0 += __shfl_xor_sync(0xffffffffu, ls0, 1);
            ls0 += __shfl_xor_sync(0xffffffffu, ls0, 2);
            ls1 += __shfl_xor_sync(0xffffffffu, ls1, 1);
            ls1 += __shfl_xor_sync(0xffffffffu, ls1, 2);
            l0 = l0 * rs0 + ls0;
            l1 = l1 * rs1 + ls1;
            #pragma unroll
            for (int i = 0; i < 8; i++) {
                oacc[i][0] *= rs0; oacc[i][1] *= rs0;
                oacc[i][2] *= rs1; oacc[i][3] *= rs1;
            }
        }

        // ---- PV ----
        #pragma unroll
        for (int ks = 0; ks < 4; ks++) {
            uint32_t ap[4], apl[4];
            {
                const float p00 = sc[2*ks][0],   p01 = sc[2*ks][1];
                const float p10 = sc[2*ks][2],   p11 = sc[2*ks][3];
                const float p20 = sc[2*ks+1][0], p21 = sc[2*ks+1][1];
                const float p30 = sc[2*ks+1][2], p31 = sc[2*ks+1][3];
                ap[0]  = packbf2(p00, p01);
                ap[1]  = packbf2(p10, p11);
                ap[2]  = packbf2(p20, p21);
                ap[3]  = packbf2(p30, p31);
                apl[0] = packbf2(bfres(p00), bfres(p01));
                apl[1] = packbf2(bfres(p10), bfres(p11));
                apl[2] = packbf2(bfres(p20), bfres(p21));
                apl[3] = packbf2(bfres(p30), bfres(p31));
            }
            #pragma unroll
            for (int hf = 0; hf < 4; hf++) {
                const int r = ks * 16 + vrow_l;
                const int u = hf * 2 + vnu;
                const uint32_t off = r * 128 + ((u ^ (r & 7)) << 4);
                uint32_t vh[2][2], vl[2][2];
                LDMX4T(vh[0][0], vh[0][1], vh[1][0], vh[1][1], sVh + off);
                LDMX4T(vl[0][0], vl[0][1], vl[1][0], vl[1][1], sVl + off);
                #pragma unroll
                for (int t = 0; t < 2; t++) {
                    MMA_BF16(oacc[2*hf+t], ap, vh[t]);
                    MMA_BF16(oacc[2*hf+t], ap, vl[t]);
                    MMA_BF16(oacc[2*hf+t], apl, vh[t]);
                }
            }
        }
        __syncthreads();
    }

    // ---- epilogue ----
    const float inv0 = 1.f / l0, inv1 = 1.f / l1;
    const int row0 = cs + wid * 16 + g;
    #pragma unroll
    for (int ni = 0; ni < 8; ni++) {
        const int d = ni * 8 + 2 * tig;
        const size_t i0 = (size_t)(b * S_ + row0) * E_ + h * 64 + d;
        const size_t i1 = (size_t)(b * S_ + row0 + 8) * E_ + h * 64 + d;
        const float v00 = oacc[ni][0] * inv0, v01 = oacc[ni][1] * inv0;
        const float v10 = oacc[ni][2] * inv1, v11 = oacc[ni][3] * inv1;
        *(uint32_t*)&g_chi[i0] = packbf2(v00, v01);
        *(uint32_t*)&g_clo[i0] = packbf2(bfres(v00), bfres(v01));
        *(uint32_t*)&g_chi[i1] = packbf2(v10, v11);
        *(uint32_t*)&g_clo[i1] = packbf2(bfres(v10), bfres(v11));
    }
}

// ---------------------------------------------------------------------------
extern "C" void kernel_launch(void* const* d_in, const int* in_sizes, int n_in,
                              void* d_out, int out_size)
{
    const float* X  = (const float*)d_in[0];
    const float* Wq = (const float*)d_in[1];
    const float* bq = (const float*)d_in[2];
    const float* Wk = (const float*)d_in[3];
    const float* bk = (const float*)d_in[4];
    const float* Wv = (const float*)d_in[5];
    const float* bv = (const float*)d_in[6];
    const float* Wo = (const float*)d_in[7];
    const float* bo = (const float*)d_in[8];
    float* out = (float*)d_out;

    cudaFuncSetAttribute(attn_kernel, cudaFuncAttributeMaxDynamicSharedMemorySize, AT_SMEM);
    cudaFuncSetAttribute(gemm_mma,    cudaFuncAttributeMaxDynamicSharedMemorySize, GEMM_SMEM);

    convert_x<<<(MTOT * E_) / (256 * 4), 256>>>(X);
    transpose_w<<<dim3(E_ / 32, E_ / 32, 4), dim3(32, 8)>>>(Wq, Wk, Wv, Wo);

    gemm_mma<<<dim3(18, MTOT / 128), 256, GEMM_SMEM>>>(1, bq, bk, bv, nullptr);

    attn_kernel<<<dim3(S_ / C_, H_, B_), 128, AT_SMEM>>>();

    gemm_mma<<<dim3(6, MTOT / 128), 256, GEMM_SMEM>>>(0, bo, nullptr, nullptr, out);
}

// round 9
// speedup vs baseline: 5.0114x; 1.2666x over previous
#include <cuda_runtime.h>
#include <cuda_bf16.h>
#include <cuda_fp16.h>
#include <math.h>
#include <stdint.h>

#define B_ 2
#define S_ 4096
#define E_ 768
#define H_ 12
#define D_ 64
#define C_ 64
#define R_ 256
#define MTOT (B_*S_)

// operands
__device__ __half         g_x16[MTOT*E_];        // X fp16 (q,k path)
__device__ __nv_bfloat16  g_xhi[MTOT*E_];        // X bf16 hi/lo (v path)
__device__ __nv_bfloat16  g_xlo[MTOT*E_];
__device__ __half         g_wqk16[2*E_*E_];      // [z*768+n][k] fp16: Wq^T, Wk^T
__device__ __nv_bfloat16  g_wt_hi[2*E_*E_];      // [z*768+n][k] bf16: Wv^T, Wo^T
__device__ __nv_bfloat16  g_wt_lo[2*E_*E_];
__device__ __half         g_q16[B_*H_*S_*D_];    // q,k fp16 (pre-scaled q)
__device__ __half         g_k16[B_*H_*S_*D_];
__device__ __nv_bfloat16  g_vhi[B_*H_*S_*D_];
__device__ __nv_bfloat16  g_vlo[B_*H_*S_*D_];
__device__ __nv_bfloat16  g_chi[MTOT*E_];
__device__ __nv_bfloat16  g_clo[MTOT*E_];

// ---------------------------------------------------------------------------
__device__ __forceinline__ uint32_t smem_u32(const void* p) {
    uint32_t a;
    asm("{ .reg .u64 t; cvta.to.shared.u64 t, %1; cvt.u32.u64 %0, t; }" : "=r"(a) : "l"(p));
    return a;
}
#define SWZ(off) ((off) ^ (((off) >> 3) & 0x70))

#define CP16(dst, src) \
    asm volatile("cp.async.cg.shared.global [%0], [%1], 16;" :: "r"(dst), "l"(src) : "memory")
#define CP_COMMIT() asm volatile("cp.async.commit_group;" ::: "memory")
#define CP_WAIT1()  asm volatile("cp.async.wait_group 1;" ::: "memory")
#define CP_WAIT0()  asm volatile("cp.async.wait_group 0;" ::: "memory")

#define LDMX4(r0, r1, r2, r3, a) \
    asm volatile("ldmatrix.sync.aligned.m8n8.x4.shared.b16 {%0,%1,%2,%3}, [%4];" \
                 : "=r"(r0), "=r"(r1), "=r"(r2), "=r"(r3) : "r"(a))
#define LDMX4T(r0, r1, r2, r3, a) \
    asm volatile("ldmatrix.sync.aligned.m8n8.x4.trans.shared.b16 {%0,%1,%2,%3}, [%4];" \
                 : "=r"(r0), "=r"(r1), "=r"(r2), "=r"(r3) : "r"(a))

#define MMA_BF16(d, a, b) \
    asm volatile("mma.sync.aligned.m16n8k16.row.col.f32.bf16.bf16.f32 " \
                 "{%0,%1,%2,%3}, {%4,%5,%6,%7}, {%8,%9}, {%0,%1,%2,%3};" \
                 : "+f"((d)[0]), "+f"((d)[1]), "+f"((d)[2]), "+f"((d)[3]) \
                 : "r"((a)[0]), "r"((a)[1]), "r"((a)[2]), "r"((a)[3]), \
                   "r"((b)[0]), "r"((b)[1]))

#define MMA_F16(d, a, b) \
    asm volatile("mma.sync.aligned.m16n8k16.row.col.f32.f16.f16.f32 " \
                 "{%0,%1,%2,%3}, {%4,%5,%6,%7}, {%8,%9}, {%0,%1,%2,%3};" \
                 : "+f"((d)[0]), "+f"((d)[1]), "+f"((d)[2]), "+f"((d)[3]) \
                 : "r"((a)[0]), "r"((a)[1]), "r"((a)[2]), "r"((a)[3]), \
                   "r"((b)[0]), "r"((b)[1]))

__device__ __forceinline__ uint32_t packbf2(float lo, float hi) {
    uint32_t r;
    asm("cvt.rn.bf16x2.f32 %0, %1, %2;" : "=r"(r) : "f"(hi), "f"(lo));
    return r;
}
__device__ __forceinline__ uint32_t packh2(float lo, float hi) {
    uint32_t r;
    asm("cvt.rn.f16x2.f32 %0, %1, %2;" : "=r"(r) : "f"(hi), "f"(lo));
    return r;
}
__device__ __forceinline__ float bfres(float x) {
    return x - __bfloat162float(__float2bfloat16(x));
}

// ---------------------------------------------------------------------------
// prep kernels
// ---------------------------------------------------------------------------
__global__ __launch_bounds__(256)
void convert_x(const float* __restrict__ X)
{
    size_t i = ((size_t)blockIdx.x * 256 + threadIdx.x) * 4;
    float4 v = *(const float4*)(X + i);
    uint2 hi, lo, h16;
    hi.x  = packbf2(v.x, v.y); hi.y  = packbf2(v.z, v.w);
    lo.x  = packbf2(bfres(v.x), bfres(v.y));
    lo.y  = packbf2(bfres(v.z), bfres(v.w));
    h16.x = packh2(v.x, v.y);  h16.y = packh2(v.z, v.w);
    *(uint2*)&g_xhi[i] = hi;
    *(uint2*)&g_xlo[i] = lo;
    *(uint2*)&g_x16[i] = h16;
}

__global__ __launch_bounds__(256)
void transpose_w(const float* __restrict__ Wq, const float* __restrict__ Wk,
                 const float* __restrict__ Wv, const float* __restrict__ Wo)
{
    __shared__ float st[32][33];
    const int z = blockIdx.z;
    const float* __restrict__ W = (z == 0) ? Wq : (z == 1) ? Wk : (z == 2) ? Wv : Wo;
    const int n0 = blockIdx.x * 32, k0 = blockIdx.y * 32;
    const int tx = threadIdx.x, ty = threadIdx.y;
    #pragma unroll
    for (int j = 0; j < 4; j++)
        st[ty + 8 * j][tx] = W[(size_t)(k0 + ty + 8 * j) * E_ + n0 + tx];
    __syncthreads();
    #pragma unroll
    for (int j = 0; j < 4; j++) {
        float v = st[tx][ty + 8 * j];
        if (z < 2) {
            size_t dst = (size_t)(z * E_ + n0 + ty + 8 * j) * E_ + k0 + tx;
            g_wqk16[dst] = __float2half(v);
        } else {
            size_t dst = (size_t)((z - 2) * E_ + n0 + ty + 8 * j) * E_ + k0 + tx;
            __nv_bfloat16 h = __float2bfloat16(v);
            g_wt_hi[dst] = h;
            g_wt_lo[dst] = __float2bfloat16(v - __bfloat162float(h));
        }
    }
}

// ---------------------------------------------------------------------------
// single-term fp16 GEMM for q,k. grid (12, 64): z = bx/6, nblk = bx%6.
// 3-stage cp.async, buffers A(16KB)+B(16KB) per stage.
// ---------------------------------------------------------------------------
#define BKC 64
#define NCH (E_/BKC)
#define BUFH 32768
#define GEMMH_SMEM (3*BUFH)     // 98304

__global__ __launch_bounds__(256)
void gemm_half(const float* __restrict__ bq, const float* __restrict__ bk)
{
    extern __shared__ char smem[];
    const uint32_t sb = smem_u32(smem);
    const int tid = threadIdx.x;
    const int wid = tid >> 5, lane = tid & 31;
    const int wm = wid >> 2, wn = wid & 3;
    const int z = blockIdx.x / 6, nblk = blockIdx.x % 6;
    const int m0 = blockIdx.y * 128, n0 = nblk * 128;

    const __half* __restrict__ A = g_x16;
    const __half* __restrict__ Bw = g_wqk16 + (size_t)z * E_ * E_;
    const float* __restrict__ bias = z ? bk : bq;
    __half* __restrict__ outArr = z ? g_k16 : g_q16;
    const float scale = z ? 1.0f : 0.125f;

    float acc[4][4][4];
    #pragma unroll
    for (int i = 0; i < 4; i++)
        #pragma unroll
        for (int j = 0; j < 4; j++)
            #pragma unroll
            for (int q = 0; q < 4; q++) acc[i][j][q] = 0.f;

    auto issue = [&](int c) {
        const uint32_t bo = sb + (c % 3) * BUFH;
        #pragma unroll
        for (int it = 0; it < 4; it++) {
            const int u = tid + 256 * it;
            const int row = u >> 3, cu = u & 7;
            const size_t ga = (size_t)(m0 + row) * E_ + c * BKC + cu * 8;
            const size_t gb = (size_t)(n0 + row) * E_ + c * BKC + cu * 8;
            const uint32_t so = SWZ((uint32_t)(row * 128 + cu * 16));
            CP16(bo + 0     + so, A + ga);
            CP16(bo + 16384 + so, Bw + gb);
        }
        CP_COMMIT();
    };

    issue(0);
    issue(1);

    const int arow = (lane & 15);
    const int au   = (lane >> 4);
    const int brow = ((lane >> 4) << 3) + (lane & 7);
    const int bu   = ((lane >> 3) & 1);

    for (int c = 0; c < NCH; c++) {
        if (c + 1 < NCH) CP_WAIT1(); else CP_WAIT0();
        __syncthreads();
        if (c + 2 < NCH) issue(c + 2);

        const uint32_t bo = sb + (c % 3) * BUFH;
        const uint32_t sA = bo, sB = bo + 16384;

        #pragma unroll
        for (int ks = 0; ks < 4; ks++) {
            uint32_t ah[4][4], bh[4][2];
            #pragma unroll
            for (int mt = 0; mt < 4; mt++) {
                const int r = wm * 64 + mt * 16 + arow;
                const int u = ks * 2 + au;
                const uint32_t off = r * 128 + ((u ^ (r & 7)) << 4);
                LDMX4(ah[mt][0], ah[mt][1], ah[mt][2], ah[mt][3], sA + off);
            }
            #pragma unroll
            for (int half2_ = 0; half2_ < 2; half2_++) {
                const int r = wn * 32 + half2_ * 16 + brow;
                const int u = ks * 2 + bu;
                const uint32_t off = r * 128 + ((u ^ (r & 7)) << 4);
                LDMX4(bh[half2_*2][0], bh[half2_*2][1], bh[half2_*2+1][0], bh[half2_*2+1][1], sB + off);
            }
            #pragma unroll
            for (int mi = 0; mi < 4; mi++)
                #pragma unroll
                for (int ni = 0; ni < 4; ni++)
                    MMA_F16(acc[mi][ni], ah[mi], bh[ni]);
        }
    }

    const int g = lane >> 2, tig = lane & 3;
    #pragma unroll
    for (int ni = 0; ni < 4; ni++) {
        const int col = n0 + wn * 32 + ni * 8 + 2 * tig;   // 0..767
        const float2 bi = *(const float2*)&bias[col];
        const int h = col >> 6, d = col & 63;
        #pragma unroll
        for (int mi = 0; mi < 4; mi++) {
            #pragma unroll
            for (int hf = 0; hf < 2; hf++) {
                const int row = m0 + wm * 64 + mi * 16 + g + hf * 8;
                const int bb = row >> 12, s = row & (S_ - 1);
                const float v0 = (acc[mi][ni][hf*2+0] + bi.x) * scale;
                const float v1 = (acc[mi][ni][hf*2+1] + bi.y) * scale;
                const size_t idx = ((size_t)(bb * H_ + h) * S_ + s) * D_ + d;
                *(uint32_t*)&outArr[idx] = packh2(v0, v1);
            }
        }
    }
}

// ---------------------------------------------------------------------------
// 3-term bf16 GEMM: vmode=1 -> V projection (out vhi/vlo); vmode=0 -> out proj.
// ---------------------------------------------------------------------------
#define BUFB 65536
#define GEMM_SMEM (3*BUFB)      // 196608

__global__ __launch_bounds__(256)
void gemm_mma(int vmode, const float* __restrict__ bias, float* __restrict__ outp)
{
    extern __shared__ char smem[];
    const uint32_t sb = smem_u32(smem);
    const int tid = threadIdx.x;
    const int wid = tid >> 5, lane = tid & 31;
    const int wm = wid >> 2, wn = wid & 3;
    const int m0 = blockIdx.y * 128, n0 = blockIdx.x * 128;

    const __nv_bfloat16* __restrict__ Ah = vmode ? g_xhi : g_chi;
    const __nv_bfloat16* __restrict__ Al = vmode ? g_xlo : g_clo;
    const __nv_bfloat16* __restrict__ Bh = g_wt_hi + (vmode ? 0 : (size_t)E_ * E_);
    const __nv_bfloat16* __restrict__ Bl = g_wt_lo + (vmode ? 0 : (size_t)E_ * E_);

    float acc[4][4][4];
    #pragma unroll
    for (int i = 0; i < 4; i++)
        #pragma unroll
        for (int j = 0; j < 4; j++)
            #pragma unroll
            for (int q = 0; q < 4; q++) acc[i][j][q] = 0.f;

    auto issue = [&](int c) {
        const uint32_t bo = sb + (c % 3) * BUFB;
        #pragma unroll
        for (int it = 0; it < 4; it++) {
            const int u = tid + 256 * it;
            const int row = u >> 3, cu = u & 7;
            const size_t ga = (size_t)(m0 + row) * E_ + c * BKC + cu * 8;
            const size_t gb = (size_t)(n0 + row) * E_ + c * BKC + cu * 8;
            const uint32_t so = SWZ((uint32_t)(row * 128 + cu * 16));
            CP16(bo + 0     + so, Ah + ga);
            CP16(bo + 16384 + so, Al + ga);
            CP16(bo + 32768 + so, Bh + gb);
            CP16(bo + 49152 + so, Bl + gb);
        }
        CP_COMMIT();
    };

    issue(0);
    issue(1);

    const int arow = (lane & 15);
    const int au   = (lane >> 4);
    const int brow = ((lane >> 4) << 3) + (lane & 7);
    const int bu   = ((lane >> 3) & 1);

    for (int c = 0; c < NCH; c++) {
        if (c + 1 < NCH) CP_WAIT1(); else CP_WAIT0();
        __syncthreads();
        if (c + 2 < NCH) issue(c + 2);

        const uint32_t bo = sb + (c % 3) * BUFB;
        const uint32_t sAh = bo, sAl = bo + 16384, sBh = bo + 32768, sBl = bo + 49152;

        #pragma unroll
        for (int ks = 0; ks < 4; ks++) {
            uint32_t ah[4][4], al[4][4], bh[4][2], bl[4][2];
            #pragma unroll
            for (int mt = 0; mt < 4; mt++) {
                const int r = wm * 64 + mt * 16 + arow;
                const int u = ks * 2 + au;
                const uint32_t off = r * 128 + ((u ^ (r & 7)) << 4);
                LDMX4(ah[mt][0], ah[mt][1], ah[mt][2], ah[mt][3], sAh + off);
                LDMX4(al[mt][0], al[mt][1], al[mt][2], al[mt][3], sAl + off);
            }
            #pragma unroll
            for (int half2_ = 0; half2_ < 2; half2_++) {
                const int r = wn * 32 + half2_ * 16 + brow;
                const int u = ks * 2 + bu;
                const uint32_t off = r * 128 + ((u ^ (r & 7)) << 4);
                LDMX4(bh[half2_*2][0], bh[half2_*2][1], bh[half2_*2+1][0], bh[half2_*2+1][1], sBh + off);
                LDMX4(bl[half2_*2][0], bl[half2_*2][1], bl[half2_*2+1][0], bl[half2_*2+1][1], sBl + off);
            }
            #pragma unroll
            for (int mi = 0; mi < 4; mi++)
                #pragma unroll
                for (int ni = 0; ni < 4; ni++) {
                    MMA_BF16(acc[mi][ni], ah[mi], bh[ni]);
                    MMA_BF16(acc[mi][ni], ah[mi], bl[ni]);
                    MMA_BF16(acc[mi][ni], al[mi], bh[ni]);
                }
        }
    }

    const int g = lane >> 2, tig = lane & 3;
    #pragma unroll
    for (int ni = 0; ni < 4; ni++) {
        const int col = n0 + wn * 32 + ni * 8 + 2 * tig;
        const float2 bi = *(const float2*)&bias[col];
        if (vmode) {
            const int h = col >> 6, d = col & 63;
            #pragma unroll
            for (int mi = 0; mi < 4; mi++) {
                #pragma unroll
                for (int hf = 0; hf < 2; hf++) {
                    const int row = m0 + wm * 64 + mi * 16 + g + hf * 8;
                    const int bb = row >> 12, s = row & (S_ - 1);
                    const float v0 = acc[mi][ni][hf*2+0] + bi.x;
                    const float v1 = acc[mi][ni][hf*2+1] + bi.y;
                    const size_t idx = ((size_t)(bb * H_ + h) * S_ + s) * D_ + d;
                    *(uint32_t*)&g_vhi[idx] = packbf2(v0, v1);
                    *(uint32_t*)&g_vlo[idx] = packbf2(bfres(v0), bfres(v1));
                }
            }
        } else {
            #pragma unroll
            for (int mi = 0; mi < 4; mi++) {
                #pragma unroll
                for (int hf = 0; hf < 2; hf++) {
                    const int row = m0 + wm * 64 + mi * 16 + g + hf * 8;
                    float2 o;
                    o.x = acc[mi][ni][hf*2+0] + bi.x;
                    o.y = acc[mi][ni][hf*2+1] + bi.y;
                    *(float2*)&outp[(size_t)row * E_ + col] = o;
                }
            }
        }
    }
}

// ---------------------------------------------------------------------------
// Flash attention: QK single fp16, PV 3-term bf16.
// Stage = Kh16(8KB) + Vhi(8KB) + Vlo(8KB) = 24KB; 2 stages = 48KB.
// ---------------------------------------------------------------------------
#define AT_STAGE 24576
#define AT_SMEM  (2*AT_STAGE)

__global__ __launch_bounds__(128, 3)
void attn_kernel()
{
    extern __shared__ char smraw[];
    const uint32_t sb = smem_u32(smraw);
    const int tid = threadIdx.x;
    const int wid = tid >> 5, lane = tid & 31;
    const int g = lane >> 2, tig = lane & 3;
    const int chunk = blockIdx.x, h = blockIdx.y, b = blockIdx.z;
    const int cs = chunk * C_;
    const size_t base = (size_t)(b * H_ + h) * S_ * D_;

    // ---- stage Q (fp16, 8KB) through stage0 area, hoist fragments ----
    uint32_t qh[4][4];
    {
        #pragma unroll
        for (int it = 0; it < 2; it++) {
            const int u = tid + 128 * it;
            const int row = u >> 2, cu = (u & 3) * 2;
            const size_t gq = base + (size_t)(cs + row) * D_ + cu * 8;
            const uint32_t so = SWZ((uint32_t)(row * 128 + cu * 16));
            CP16(sb + so, g_q16 + gq);
            CP16(sb + SWZ((uint32_t)(row * 128 + (cu + 1) * 16)), g_q16 + gq + 8);
        }
        CP_COMMIT();
        CP_WAIT0();
        __syncthreads();
        const int qrow = wid * 16 + (lane & 15);
        const int qau  = (lane >> 4);
        #pragma unroll
        for (int ks = 0; ks < 4; ks++) {
            const int u = ks * 2 + qau;
            const uint32_t off = qrow * 128 + ((u ^ (qrow & 7)) << 4);
            LDMX4(qh[ks][0], qh[ks][1], qh[ks][2], qh[ks][3], sb + off);
        }
        __syncthreads();
    }

    const int t0 = (cs < R_) ? (R_ - cs) / C_ : 0;
    const int t1e = (S_ - cs + R_) / C_;
    const int t1 = (t1e < 9) ? t1e : 9;
    const int ntiles = t1 - t0;

    auto issueKV = [&](int t, int buf) {
        const int tstart = cs - R_ + t * C_;
        const uint32_t bo = sb + buf * AT_STAGE;
        #pragma unroll
        for (int it = 0; it < 4; it++) {
            const int u = tid + 128 * it;
            const int row = u >> 3, cu = u & 7;
            const size_t gk = base + (size_t)(tstart + row) * D_ + cu * 8;
            const uint32_t so = SWZ((uint32_t)(row * 128 + cu * 16));
            CP16(bo + 0     + so, g_k16 + gk);
            CP16(bo + 8192  + so, g_vhi + gk);
            CP16(bo + 16384 + so, g_vlo + gk);
        }
        CP_COMMIT();
    };

    issueKV(t0, 0);

    float oacc[8][4];
    #pragma unroll
    for (int i = 0; i < 8; i++)
        #pragma unroll
        for (int j = 0; j < 4; j++) oacc[i][j] = 0.f;
    float m0 = -INFINITY, m1 = -INFINITY, l0 = 0.f, l1 = 0.f;

    const int kbrow = ((lane >> 4) << 3) + (lane & 7);
    const int kbu   = ((lane >> 3) & 1);
    const int vrow_l = (lane & 7) + 8 * ((lane >> 3) & 1);
    const int vnu    = (lane >> 4);

    for (int tt = 0; tt < ntiles; tt++) {
        if (tt + 1 < ntiles) { issueKV(t0 + tt + 1, (tt + 1) & 1); CP_WAIT1(); }
        else                 { CP_WAIT0(); }
        __syncthreads();

        const uint32_t bo = sb + (tt & 1) * AT_STAGE;
        const uint32_t sKh = bo, sVh = bo + 8192, sVl = bo + 16384;

        // ---- QK (single fp16) ----
        float sc[8][4];
        #pragma unroll
        for (int i = 0; i < 8; i++)
            #pragma unroll
            for (int j = 0; j < 4; j++) sc[i][j] = 0.f;

        #pragma unroll
        for (int ks = 0; ks < 4; ks++) {
            #pragma unroll
            for (int hf = 0; hf < 4; hf++) {
                const int r = hf * 16 + kbrow;
                const int u = ks * 2 + kbu;
                const uint32_t off = r * 128 + ((u ^ (r & 7)) << 4);
                uint32_t bh[2][2];
                LDMX4(bh[0][0], bh[0][1], bh[1][0], bh[1][1], sKh + off);
                MMA_F16(sc[2*hf+0], qh[ks], bh[0]);
                MMA_F16(sc[2*hf+1], qh[ks], bh[1]);
            }
        }

        // ---- online softmax ----
        {
            float mx0 = sc[0][0], mx1 = sc[0][2];
            #pragma unroll
            for (int i = 0; i < 8; i++) {
                mx0 = fmaxf(mx0, fmaxf(sc[i][0], sc[i][1]));
                mx1 = fmaxf(mx1, fmaxf(sc[i][2], sc[i][3]));
            }
            mx0 = fmaxf(mx0, __shfl_xor_sync(0xffffffffu, mx0, 1));
            mx0 = fmaxf(mx0, __shfl_xor_sync(0xffffffffu, mx0, 2));
            mx1 = fmaxf(mx1, __shfl_xor_sync(0xffffffffu, mx1, 1));
            mx1 = fmaxf(mx1, __shfl_xor_sync(0xffffffffu, mx1, 2));
            const float mn0 = fmaxf(m0, mx0), mn1 = fmaxf(m1, mx1);
            const float rs0 = __expf(m0 - mn0), rs1 = __expf(m1 - mn1);
            m0 = mn0; m1 = mn1;
            float ls0 = 0.f, ls1 = 0.f;
            #pragma unroll
            for (int i = 0; i < 8; i++) {
                sc[i][0] = __expf(sc[i][0] - mn0);
                sc[i][1] = __expf(sc[i][1] - mn0);
                sc[i][2] = __expf(sc[i][2] - mn1);
                sc[i][3] = __expf(sc[i][3] - mn1);
                ls0 += sc[i][0] + sc[i][1];
                ls1 += sc[i][2] + sc[i][3];
            }
            ls0 += __shfl_xor_sync(0xffffffffu, ls0, 1);
            ls0 += __shfl_xor_sync(0xffffffffu, ls0, 2);
            ls1 += __shfl_xor_sync(0xffffffffu, ls1, 1);
            ls1 += __shfl_xor_sync(0xffffffffu, ls1, 2);
            l0 = l0 * rs0 + ls0;
            l1 = l1 * rs1 + ls1;
            #pragma unroll
            for (int i = 0; i < 8; i++) {
                oacc[i][0] *= rs0; oacc[i][1] *= rs0;
                oacc[i][2] *= rs1; oacc[i][3] *= rs1;
            }
        }

        // ---- PV (3-term bf16) ----
        #pragma unroll
        for (int ks = 0; ks < 4; ks++) {
            uint32_t ap[4], apl[4];
            {
                const float p00 = sc[2*ks][0],   p01 = sc[2*ks][1];
                const float p10 = sc[2*ks][2],   p11 = sc[2*ks][3];
                const float p20 = sc[2*ks+1][0], p21 = sc[2*ks+1][1];
                const float p30 = sc[2*ks+1][2], p31 = sc[2*ks+1][3];
                ap[0]  = packbf2(p00, p01);
                ap[1]  = packbf2(p10, p11);
                ap[2]  = packbf2(p20, p21);
                ap[3]  = packbf2(p30, p31);
                apl[0] = packbf2(bfres(p00), bfres(p01));
                apl[1] = packbf2(bfres(p10), bfres(p11));
                apl[2] = packbf2(bfres(p20), bfres(p21));
                apl[3] = packbf2(bfres(p30), bfres(p31));
            }
            #pragma unroll
            for (int hf = 0; hf < 4; hf++) {
                const int r = ks * 16 + vrow_l;
                const int u = hf * 2 + vnu;
                const uint32_t off = r * 128 + ((u ^ (r & 7)) << 4);
                uint32_t vh[2][2], vl[2][2];
                LDMX4T(vh[0][0], vh[0][1], vh[1][0], vh[1][1], sVh + off);
                LDMX4T(vl[0][0], vl[0][1], vl[1][0], vl[1][1], sVl + off);
                #pragma unroll
                for (int t = 0; t < 2; t++) {
                    MMA_BF16(oacc[2*hf+t], ap, vh[t]);
                    MMA_BF16(oacc[2*hf+t], ap, vl[t]);
                    MMA_BF16(oacc[2*hf+t], apl, vh[t]);
                }
            }
        }
        __syncthreads();
    }

    // ---- epilogue ----
    const float inv0 = 1.f / l0, inv1 = 1.f / l1;
    const int row0 = cs + wid * 16 + g;
    #pragma unroll
    for (int ni = 0; ni < 8; ni++) {
        const int d = ni * 8 + 2 * tig;
        const size_t i0 = (size_t)(b * S_ + row0) * E_ + h * 64 + d;
        const size_t i1 = (size_t)(b * S_ + row0 + 8) * E_ + h * 64 + d;
        const float v00 = oacc[ni][0] * inv0, v01 = oacc[ni][1] * inv0;
        const float v10 = oacc[ni][2] * inv1, v11 = oacc[ni][3] * inv1;
        *(uint32_t*)&g_chi[i0] = packbf2(v00, v01);
        *(uint32_t*)&g_clo[i0] = packbf2(bfres(v00), bfres(v01));
        *(uint32_t*)&g_chi[i1] = packbf2(v10, v11);
        *(uint32_t*)&g_clo[i1] = packbf2(bfres(v10), bfres(v11));
    }
}

// ---------------------------------------------------------------------------
extern "C" void kernel_launch(void* const* d_in, const int* in_sizes, int n_in,
                              void* d_out, int out_size)
{
    const float* X  = (const float*)d_in[0];
    const float* Wq = (const float*)d_in[1];
    const float* bq = (const float*)d_in[2];
    const float* Wk = (const float*)d_in[3];
    const float* bk = (const float*)d_in[4];
    const float* Wv = (const float*)d_in[5];
    const float* bv = (const float*)d_in[6];
    const float* Wo = (const float*)d_in[7];
    const float* bo = (const float*)d_in[8];
    float* out = (float*)d_out;

    cudaFuncSetAttribute(attn_kernel, cudaFuncAttributeMaxDynamicSharedMemorySize, AT_SMEM);
    cudaFuncSetAttribute(gemm_mma,    cudaFuncAttributeMaxDynamicSharedMemorySize, GEMM_SMEM);
    cudaFuncSetAttribute(gemm_half,   cudaFuncAttributeMaxDynamicSharedMemorySize, GEMMH_SMEM);

    convert_x<<<(MTOT * E_) / (256 * 4), 256>>>(X);
    transpose_w<<<dim3(E_ / 32, E_ / 32, 4), dim3(32, 8)>>>(Wq, Wk, Wv, Wo);

    gemm_half<<<dim3(12, MTOT / 128), 256, GEMMH_SMEM>>>(bq, bk);
    gemm_mma<<<dim3(6, MTOT / 128), 256, GEMM_SMEM>>>(1, bv, nullptr);

    attn_kernel<<<dim3(S_ / C_, H_, B_), 128, AT_SMEM>>>();

    gemm_mma<<<dim3(6, MTOT / 128), 256, GEMM_SMEM>>>(0, bo, out);
}

// round 10
// speedup vs baseline: 6.4407x; 1.2852x over previous
#include <cuda_runtime.h>
#include <cuda_fp16.h>
#include <math.h>
#include <stdint.h>

#define B_ 2
#define S_ 4096
#define E_ 768
#define H_ 12
#define D_ 64
#define C_ 64
#define R_ 256
#define MTOT (B_*S_)

// fp16 operands
__device__ __half g_x16 [MTOT*E_];      // X hi
__device__ __half g_x16l[MTOT*E_];      // X residual
__device__ __half g_w16 [4*E_*E_];      // [z*768+n][k]: Wq^T,Wk^T,Wv^T,Wo^T (single fp16)
__device__ __half g_q16 [B_*H_*S_*D_];  // q (pre-scaled), k : single fp16
__device__ __half g_k16 [B_*H_*S_*D_];
__device__ __half g_vhi [B_*H_*S_*D_];  // v hi/lo
__device__ __half g_vlo [B_*H_*S_*D_];
__device__ __half g_chi [MTOT*E_];      // ctx hi/lo
__device__ __half g_clo [MTOT*E_];

// ---------------------------------------------------------------------------
__device__ __forceinline__ uint32_t smem_u32(const void* p) {
    uint32_t a;
    asm("{ .reg .u64 t; cvta.to.shared.u64 t, %1; cvt.u32.u64 %0, t; }" : "=r"(a) : "l"(p));
    return a;
}
#define SWZ(off) ((off) ^ (((off) >> 3) & 0x70))

#define CP16(dst, src) \
    asm volatile("cp.async.cg.shared.global [%0], [%1], 16;" :: "r"(dst), "l"(src) : "memory")
#define CP_COMMIT() asm volatile("cp.async.commit_group;" ::: "memory")
#define CP_WAIT1()  asm volatile("cp.async.wait_group 1;" ::: "memory")
#define CP_WAIT0()  asm volatile("cp.async.wait_group 0;" ::: "memory")

#define LDMX4(r0, r1, r2, r3, a) \
    asm volatile("ldmatrix.sync.aligned.m8n8.x4.shared.b16 {%0,%1,%2,%3}, [%4];" \
                 : "=r"(r0), "=r"(r1), "=r"(r2), "=r"(r3) : "r"(a))
#define LDMX4T(r0, r1, r2, r3, a) \
    asm volatile("ldmatrix.sync.aligned.m8n8.x4.trans.shared.b16 {%0,%1,%2,%3}, [%4];" \
                 : "=r"(r0), "=r"(r1), "=r"(r2), "=r"(r3) : "r"(a))

#define MMA_F16(d, a, b) \
    asm volatile("mma.sync.aligned.m16n8k16.row.col.f32.f16.f16.f32 " \
                 "{%0,%1,%2,%3}, {%4,%5,%6,%7}, {%8,%9}, {%0,%1,%2,%3};" \
                 : "+f"((d)[0]), "+f"((d)[1]), "+f"((d)[2]), "+f"((d)[3]) \
                 : "r"((a)[0]), "r"((a)[1]), "r"((a)[2]), "r"((a)[3]), \
                   "r"((b)[0]), "r"((b)[1]))

__device__ __forceinline__ uint32_t packh2(float lo, float hi) {
    uint32_t r;
    asm("cvt.rn.f16x2.f32 %0, %1, %2;" : "=r"(r) : "f"(hi), "f"(lo));
    return r;
}
__device__ __forceinline__ float hres(float x) {
    return x - __half2float(__float2half(x));
}

// ---------------------------------------------------------------------------
// prep
// ---------------------------------------------------------------------------
__global__ __launch_bounds__(256)
void convert_x(const float* __restrict__ X)
{
    size_t i = ((size_t)blockIdx.x * 256 + threadIdx.x) * 4;
    float4 v = *(const float4*)(X + i);
    uint2 hi, lo;
    hi.x = packh2(v.x, v.y);             hi.y = packh2(v.z, v.w);
    lo.x = packh2(hres(v.x), hres(v.y)); lo.y = packh2(hres(v.z), hres(v.w));
    *(uint2*)&g_x16 [i] = hi;
    *(uint2*)&g_x16l[i] = lo;
}

__global__ __launch_bounds__(256)
void transpose_w(const float* __restrict__ Wq, const float* __restrict__ Wk,
                 const float* __restrict__ Wv, const float* __restrict__ Wo)
{
    __shared__ float st[32][33];
    const int z = blockIdx.z;
    const float* __restrict__ W = (z == 0) ? Wq : (z == 1) ? Wk : (z == 2) ? Wv : Wo;
    const int n0 = blockIdx.x * 32, k0 = blockIdx.y * 32;
    const int tx = threadIdx.x, ty = threadIdx.y;
    #pragma unroll
    for (int j = 0; j < 4; j++)
        st[ty + 8 * j][tx] = W[(size_t)(k0 + ty + 8 * j) * E_ + n0 + tx];
    __syncthreads();
    #pragma unroll
    for (int j = 0; j < 4; j++)
        g_w16[(size_t)(z * E_ + n0 + ty + 8 * j) * E_ + k0 + tx] =
            __float2half(st[tx][ty + 8 * j]);
}

// ---------------------------------------------------------------------------
// 1-term fp16 GEMM for q,k. grid (12, 64).
// ---------------------------------------------------------------------------
#define BKC 64
#define NCH (E_/BKC)
#define BUFH 32768
#define GEMMH_SMEM (3*BUFH)

__global__ __launch_bounds__(256)
void gemm_half(const float* __restrict__ bq, const float* __restrict__ bk)
{
    extern __shared__ char smem[];
    const uint32_t sb = smem_u32(smem);
    const int tid = threadIdx.x;
    const int wid = tid >> 5, lane = tid & 31;
    const int wm = wid >> 2, wn = wid & 3;
    const int z = blockIdx.x / 6, nblk = blockIdx.x % 6;
    const int m0 = blockIdx.y * 128, n0 = nblk * 128;

    const __half* __restrict__ A  = g_x16;
    const __half* __restrict__ Bw = g_w16 + (size_t)z * E_ * E_;
    const float* __restrict__ bias = z ? bk : bq;
    __half* __restrict__ outArr = z ? g_k16 : g_q16;
    const float scale = z ? 1.0f : 0.125f;

    float acc[4][4][4];
    #pragma unroll
    for (int i = 0; i < 4; i++)
        #pragma unroll
        for (int j = 0; j < 4; j++)
            #pragma unroll
            for (int q = 0; q < 4; q++) acc[i][j][q] = 0.f;

    auto issue = [&](int c) {
        const uint32_t bo = sb + (c % 3) * BUFH;
        #pragma unroll
        for (int it = 0; it < 4; it++) {
            const int u = tid + 256 * it;
            const int row = u >> 3, cu = u & 7;
            const size_t ga = (size_t)(m0 + row) * E_ + c * BKC + cu * 8;
            const size_t gb = (size_t)(n0 + row) * E_ + c * BKC + cu * 8;
            const uint32_t so = SWZ((uint32_t)(row * 128 + cu * 16));
            CP16(bo + 0     + so, A + ga);
            CP16(bo + 16384 + so, Bw + gb);
        }
        CP_COMMIT();
    };

    issue(0);
    issue(1);

    const int arow = (lane & 15);
    const int au   = (lane >> 4);
    const int brow = ((lane >> 4) << 3) + (lane & 7);
    const int bu   = ((lane >> 3) & 1);

    for (int c = 0; c < NCH; c++) {
        if (c + 1 < NCH) CP_WAIT1(); else CP_WAIT0();
        __syncthreads();
        if (c + 2 < NCH) issue(c + 2);

        const uint32_t bo = sb + (c % 3) * BUFH;
        const uint32_t sA = bo, sB = bo + 16384;

        #pragma unroll
        for (int ks = 0; ks < 4; ks++) {
            uint32_t ah[4][4], bh[4][2];
            #pragma unroll
            for (int mt = 0; mt < 4; mt++) {
                const int r = wm * 64 + mt * 16 + arow;
                const int u = ks * 2 + au;
                const uint32_t off = r * 128 + ((u ^ (r & 7)) << 4);
                LDMX4(ah[mt][0], ah[mt][1], ah[mt][2], ah[mt][3], sA + off);
            }
            #pragma unroll
            for (int hv = 0; hv < 2; hv++) {
                const int r = wn * 32 + hv * 16 + brow;
                const int u = ks * 2 + bu;
                const uint32_t off = r * 128 + ((u ^ (r & 7)) << 4);
                LDMX4(bh[hv*2][0], bh[hv*2][1], bh[hv*2+1][0], bh[hv*2+1][1], sB + off);
            }
            #pragma unroll
            for (int mi = 0; mi < 4; mi++)
                #pragma unroll
                for (int ni = 0; ni < 4; ni++)
                    MMA_F16(acc[mi][ni], ah[mi], bh[ni]);
        }
    }

    const int g = lane >> 2, tig = lane & 3;
    #pragma unroll
    for (int ni = 0; ni < 4; ni++) {
        const int col = n0 + wn * 32 + ni * 8 + 2 * tig;
        const float2 bi = *(const float2*)&bias[col];
        const int h = col >> 6, d = col & 63;
        #pragma unroll
        for (int mi = 0; mi < 4; mi++) {
            #pragma unroll
            for (int hf = 0; hf < 2; hf++) {
                const int row = m0 + wm * 64 + mi * 16 + g + hf * 8;
                const int bb = row >> 12, s = row & (S_ - 1);
                const float v0 = (acc[mi][ni][hf*2+0] + bi.x) * scale;
                const float v1 = (acc[mi][ni][hf*2+1] + bi.y) * scale;
                *(uint32_t*)&outArr[((size_t)(bb * H_ + h) * S_ + s) * D_ + d] = packh2(v0, v1);
            }
        }
    }
}

// ---------------------------------------------------------------------------
// 2-term fp16 GEMM: A hi/lo x B single.
//   vmode=1: A = X, B = Wv^T, out -> g_vhi/g_vlo (b,h,s,d) + bv
//   vmode=0: A = ctx, B = Wo^T, out -> fp32 + bo
// Stage: Ah(16KB)+Al(16KB)+B(16KB) = 48KB, 3 stages = 144KB.
// ---------------------------------------------------------------------------
#define BUF2 49152
#define GEMM2_SMEM (3*BUF2)

__global__ __launch_bounds__(256)
void gemm2(int vmode, const float* __restrict__ bias, float* __restrict__ outp)
{
    extern __shared__ char smem[];
    const uint32_t sb = smem_u32(smem);
    const int tid = threadIdx.x;
    const int wid = tid >> 5, lane = tid & 31;
    const int wm = wid >> 2, wn = wid & 3;
    const int m0 = blockIdx.y * 128, n0 = blockIdx.x * 128;

    const __half* __restrict__ Ah = vmode ? g_x16  : g_chi;
    const __half* __restrict__ Al = vmode ? g_x16l : g_clo;
    const __half* __restrict__ Bw = g_w16 + (size_t)(vmode ? 2 : 3) * E_ * E_;

    float acc[4][4][4];
    #pragma unroll
    for (int i = 0; i < 4; i++)
        #pragma unroll
        for (int j = 0; j < 4; j++)
            #pragma unroll
            for (int q = 0; q < 4; q++) acc[i][j][q] = 0.f;

    auto issue = [&](int c) {
        const uint32_t bo = sb + (c % 3) * BUF2;
        #pragma unroll
        for (int it = 0; it < 4; it++) {
            const int u = tid + 256 * it;
            const int row = u >> 3, cu = u & 7;
            const size_t ga = (size_t)(m0 + row) * E_ + c * BKC + cu * 8;
            const size_t gb = (size_t)(n0 + row) * E_ + c * BKC + cu * 8;
            const uint32_t so = SWZ((uint32_t)(row * 128 + cu * 16));
            CP16(bo + 0     + so, Ah + ga);
            CP16(bo + 16384 + so, Al + ga);
            CP16(bo + 32768 + so, Bw + gb);
        }
        CP_COMMIT();
    };

    issue(0);
    issue(1);

    const int arow = (lane & 15);
    const int au   = (lane >> 4);
    const int brow = ((lane >> 4) << 3) + (lane & 7);
    const int bu   = ((lane >> 3) & 1);

    for (int c = 0; c < NCH; c++) {
        if (c + 1 < NCH) CP_WAIT1(); else CP_WAIT0();
        __syncthreads();
        if (c + 2 < NCH) issue(c + 2);

        const uint32_t bo = sb + (c % 3) * BUF2;
        const uint32_t sAh = bo, sAl = bo + 16384, sB = bo + 32768;

        #pragma unroll
        for (int ks = 0; ks < 4; ks++) {
            uint32_t ah[4][4], al[4][4], bh[4][2];
            #pragma unroll
            for (int mt = 0; mt < 4; mt++) {
                const int r = wm * 64 + mt * 16 + arow;
                const int u = ks * 2 + au;
                const uint32_t off = r * 128 + ((u ^ (r & 7)) << 4);
                LDMX4(ah[mt][0], ah[mt][1], ah[mt][2], ah[mt][3], sAh + off);
                LDMX4(al[mt][0], al[mt][1], al[mt][2], al[mt][3], sAl + off);
            }
            #pragma unroll
            for (int hv = 0; hv < 2; hv++) {
                const int r = wn * 32 + hv * 16 + brow;
                const int u = ks * 2 + bu;
                const uint32_t off = r * 128 + ((u ^ (r & 7)) << 4);
                LDMX4(bh[hv*2][0], bh[hv*2][1], bh[hv*2+1][0], bh[hv*2+1][1], sB + off);
            }
            #pragma unroll
            for (int mi = 0; mi < 4; mi++)
                #pragma unroll
                for (int ni = 0; ni < 4; ni++) {
                    MMA_F16(acc[mi][ni], ah[mi], bh[ni]);
                    MMA_F16(acc[mi][ni], al[mi], bh[ni]);
                }
        }
    }

    const int g = lane >> 2, tig = lane & 3;
    #pragma unroll
    for (int ni = 0; ni < 4; ni++) {
        const int col = n0 + wn * 32 + ni * 8 + 2 * tig;
        const float2 bi = *(const float2*)&bias[col];
        if (vmode) {
            const int h = col >> 6, d = col & 63;
            #pragma unroll
            for (int mi = 0; mi < 4; mi++) {
                #pragma unroll
                for (int hf = 0; hf < 2; hf++) {
                    const int row = m0 + wm * 64 + mi * 16 + g + hf * 8;
                    const int bb = row >> 12, s = row & (S_ - 1);
                    const float v0 = acc[mi][ni][hf*2+0] + bi.x;
                    const float v1 = acc[mi][ni][hf*2+1] + bi.y;
                    const size_t idx = ((size_t)(bb * H_ + h) * S_ + s) * D_ + d;
                    *(uint32_t*)&g_vhi[idx] = packh2(v0, v1);
                    *(uint32_t*)&g_vlo[idx] = packh2(hres(v0), hres(v1));
                }
            }
        } else {
            #pragma unroll
            for (int mi = 0; mi < 4; mi++) {
                #pragma unroll
                for (int hf = 0; hf < 2; hf++) {
                    const int row = m0 + wm * 64 + mi * 16 + g + hf * 8;
                    float2 o;
                    o.x = acc[mi][ni][hf*2+0] + bi.x;
                    o.y = acc[mi][ni][hf*2+1] + bi.y;
                    *(float2*)&outp[(size_t)row * E_ + col] = o;
                }
            }
        }
    }
}

// ---------------------------------------------------------------------------
// Flash attention: QK 1-term fp16, PV = P(single) x V(hi/lo) 2-term.
// Stage = K(8KB)+Vhi(8KB)+Vlo(8KB) = 24KB; 2 stages = 48KB.
// ---------------------------------------------------------------------------
#define AT_STAGE 24576
#define AT_SMEM  (2*AT_STAGE)

__global__ __launch_bounds__(128, 3)
void attn_kernel()
{
    extern __shared__ char smraw[];
    const uint32_t sb = smem_u32(smraw);
    const int tid = threadIdx.x;
    const int wid = tid >> 5, lane = tid & 31;
    const int g = lane >> 2, tig = lane & 3;
    const int chunk = blockIdx.x, h = blockIdx.y, b = blockIdx.z;
    const int cs = chunk * C_;
    const size_t base = (size_t)(b * H_ + h) * S_ * D_;

    // stage Q (fp16, 8KB) through stage0, hoist fragments
    uint32_t qh[4][4];
    {
        #pragma unroll
        for (int it = 0; it < 2; it++) {
            const int u = tid + 128 * it;
            const int row = u >> 2, cu = (u & 3) * 2;
            const size_t gq = base + (size_t)(cs + row) * D_ + cu * 8;
            CP16(sb + SWZ((uint32_t)(row * 128 + cu * 16)), g_q16 + gq);
            CP16(sb + SWZ((uint32_t)(row * 128 + (cu + 1) * 16)), g_q16 + gq + 8);
        }
        CP_COMMIT();
        CP_WAIT0();
        __syncthreads();
        const int qrow = wid * 16 + (lane & 15);
        const int qau  = (lane >> 4);
        #pragma unroll
        for (int ks = 0; ks < 4; ks++) {
            const int u = ks * 2 + qau;
            const uint32_t off = qrow * 128 + ((u ^ (qrow & 7)) << 4);
            LDMX4(qh[ks][0], qh[ks][1], qh[ks][2], qh[ks][3], sb + off);
        }
        __syncthreads();
    }

    const int t0 = (cs < R_) ? (R_ - cs) / C_ : 0;
    const int t1e = (S_ - cs + R_) / C_;
    const int t1 = (t1e < 9) ? t1e : 9;
    const int ntiles = t1 - t0;

    auto issueKV = [&](int t, int buf) {
        const int tstart = cs - R_ + t * C_;
        const uint32_t bo = sb + buf * AT_STAGE;
        #pragma unroll
        for (int it = 0; it < 4; it++) {
            const int u = tid + 128 * it;
            const int row = u >> 3, cu = u & 7;
            const size_t gk = base + (size_t)(tstart + row) * D_ + cu * 8;
            const uint32_t so = SWZ((uint32_t)(row * 128 + cu * 16));
            CP16(bo + 0     + so, g_k16 + gk);
            CP16(bo + 8192  + so, g_vhi + gk);
            CP16(bo + 16384 + so, g_vlo + gk);
        }
        CP_COMMIT();
    };

    issueKV(t0, 0);

    float oacc[8][4];
    #pragma unroll
    for (int i = 0; i < 8; i++)
        #pragma unroll
        for (int j = 0; j < 4; j++) oacc[i][j] = 0.f;
    float m0 = -INFINITY, m1 = -INFINITY, l0 = 0.f, l1 = 0.f;

    const int kbrow = ((lane >> 4) << 3) + (lane & 7);
    const int kbu   = ((lane >> 3) & 1);
    const int vrow_l = (lane & 7) + 8 * ((lane >> 3) & 1);
    const int vnu    = (lane >> 4);

    for (int tt = 0; tt < ntiles; tt++) {
        if (tt + 1 < ntiles) { issueKV(t0 + tt + 1, (tt + 1) & 1); CP_WAIT1(); }
        else                 { CP_WAIT0(); }
        __syncthreads();

        const uint32_t bo = sb + (tt & 1) * AT_STAGE;
        const uint32_t sKh = bo, sVh = bo + 8192, sVl = bo + 16384;

        // QK (1-term fp16)
        float sc[8][4];
        #pragma unroll
        for (int i = 0; i < 8; i++)
            #pragma unroll
            for (int j = 0; j < 4; j++) sc[i][j] = 0.f;

        #pragma unroll
        for (int ks = 0; ks < 4; ks++) {
            #pragma unroll
            for (int hf = 0; hf < 4; hf++) {
                const int r = hf * 16 + kbrow;
                const int u = ks * 2 + kbu;
                const uint32_t off = r * 128 + ((u ^ (r & 7)) << 4);
                uint32_t bh[2][2];
                LDMX4(bh[0][0], bh[0][1], bh[1][0], bh[1][1], sKh + off);
                MMA_F16(sc[2*hf+0], qh[ks], bh[0]);
                MMA_F16(sc[2*hf+1], qh[ks], bh[1]);
            }
        }

        // online softmax
        {
            float mx0 = sc[0][0], mx1 = sc[0][2];
            #pragma unroll
            for (int i = 0; i < 8; i++) {
                mx0 = fmaxf(mx0, fmaxf(sc[i][0], sc[i][1]));
                mx1 = fmaxf(mx1, fmaxf(sc[i][2], sc[i][3]));
            }
            mx0 = fmaxf(mx0, __shfl_xor_sync(0xffffffffu, mx0, 1));
            mx0 = fmaxf(mx0, __shfl_xor_sync(0xffffffffu, mx0, 2));
            mx1 = fmaxf(mx1, __shfl_xor_sync(0xffffffffu, mx1, 1));
            mx1 = fmaxf(mx1, __shfl_xor_sync(0xffffffffu, mx1, 2));
            const float mn0 = fmaxf(m0, mx0), mn1 = fmaxf(m1, mx1);
            const float rs0 = __expf(m0 - mn0), rs1 = __expf(m1 - mn1);
            m0 = mn0; m1 = mn1;
            float ls0 = 0.f, ls1 = 0.f;
            #pragma unroll
            for (int i = 0; i < 8; i++) {
                sc[i][0] = __expf(sc[i][0] - mn0);
                sc[i][1] = __expf(sc[i][1] - mn0);
                sc[i][2] = __expf(sc[i][2] - mn1);
                sc[i][3] = __expf(sc[i][3] - mn1);
                ls0 += sc[i][0] + sc[i][1];
                ls1 += sc[i][2] + sc[i][3];
            }
            ls0 += __shfl_xor_sync(0xffffffffu, ls0, 1);
            ls0 += __shfl_xor_sync(0xffffffffu, ls0, 2);
            ls1 += __shfl_xor_sync(0xffffffffu, ls1, 1);
            ls1 += __shfl_xor_sync(0xffffffffu, ls1, 2);
            l0 = l0 * rs0 + ls0;
            l1 = l1 * rs1 + ls1;
            #pragma unroll
            for (int i = 0; i < 8; i++) {
                oacc[i][0] *= rs0; oacc[i][1] *= rs0;
                oacc[i][2] *= rs1; oacc[i][3] *= rs1;
            }
        }

        // PV: P single x V hi/lo
        #pragma unroll
        for (int ks = 0; ks < 4; ks++) {
            uint32_t ap[4];
            ap[0] = packh2(sc[2*ks][0],   sc[2*ks][1]);
            ap[1] = packh2(sc[2*ks][2],   sc[2*ks][3]);
            ap[2] = packh2(sc[2*ks+1][0], sc[2*ks+1][1]);
            ap[3] = packh2(sc[2*ks+1][2], sc[2*ks+1][3]);
            #pragma unroll
            for (int hf = 0; hf < 4; hf++) {
                const int r = ks * 16 + vrow_l;
                const int u = hf * 2 + vnu;
                const uint32_t off = r * 128 + ((u ^ (r & 7)) << 4);
                uint32_t vh[2][2], vl[2][2];
                LDMX4T(vh[0][0], vh[0][1], vh[1][0], vh[1][1], sVh + off);
                LDMX4T(vl[0][0], vl[0][1], vl[1][0], vl[1][1], sVl + off);
                #pragma unroll
                for (int t = 0; t < 2; t++) {
                    MMA_F16(oacc[2*hf+t], ap, vh[t]);
                    MMA_F16(oacc[2*hf+t], ap, vl[t]);
                }
            }
        }
        __syncthreads();
    }

    // epilogue -> ctx fp16 hi/lo
    const float inv0 = 1.f / l0, inv1 = 1.f / l1;
    const int row0 = cs + wid * 16 + g;
    #pragma unroll
    for (int ni = 0; ni < 8; ni++) {
        const int d = ni * 8 + 2 * tig;
        const size_t i0 = (size_t)(b * S_ + row0) * E_ + h * 64 + d;
        const size_t i1 = (size_t)(b * S_ + row0 + 8) * E_ + h * 64 + d;
        const float v00 = oacc[ni][0] * inv0, v01 = oacc[ni][1] * inv0;
        const float v10 = oacc[ni][2] * inv1, v11 = oacc[ni][3] * inv1;
        *(uint32_t*)&g_chi[i0] = packh2(v00, v01);
        *(uint32_t*)&g_clo[i0] = packh2(hres(v00), hres(v01));
        *(uint32_t*)&g_chi[i1] = packh2(v10, v11);
        *(uint32_t*)&g_clo[i1] = packh2(hres(v10), hres(v11));
    }
}

// ---------------------------------------------------------------------------
extern "C" void kernel_launch(void* const* d_in, const int* in_sizes, int n_in,
                              void* d_out, int out_size)
{
    const float* X  = (const float*)d_in[0];
    const float* Wq = (const float*)d_in[1];
    const float* bq = (const float*)d_in[2];
    const float* Wk = (const float*)d_in[3];
    const float* bk = (const float*)d_in[4];
    const float* Wv = (const float*)d_in[5];
    const float* bv = (const float*)d_in[6];
    const float* Wo = (const float*)d_in[7];
    const float* bo = (const float*)d_in[8];
    float* out = (float*)d_out;

    cudaFuncSetAttribute(attn_kernel, cudaFuncAttributeMaxDynamicSharedMemorySize, AT_SMEM);
    cudaFuncSetAttribute(gemm2,       cudaFuncAttributeMaxDynamicSharedMemorySize, GEMM2_SMEM);
    cudaFuncSetAttribute(gemm_half,   cudaFuncAttributeMaxDynamicSharedMemorySize, GEMMH_SMEM);

    convert_x<<<(MTOT * E_) / (256 * 4), 256>>>(X);
    transpose_w<<<dim3(E_ / 32, E_ / 32, 4), dim3(32, 8)>>>(Wq, Wk, Wv, Wo);

    gemm_half<<<dim3(12, MTOT / 128), 256, GEMMH_SMEM>>>(bq, bk);
    gemm2<<<dim3(6, MTOT / 128), 256, GEMM2_SMEM>>>(1, bv, nullptr);

    attn_kernel<<<dim3(S_ / C_, H_, B_), 128, AT_SMEM>>>();

    gemm2<<<dim3(6, MTOT / 128), 256, GEMM2_SMEM>>>(0, bo, out);
}